// round 10
// baseline (speedup 1.0000x reference)
#include <cuda_runtime.h>
#include <cuda_bf16.h>
#include <cstdint>

#define D_MODEL 1024
#define NH 16
#define HD 64
#define BB 2
#define TT 2048
#define MTOT (BB*TT)   // 4096

// bf16 hi/lo split scratch: activations 3 slices (q,k,v; att reuses slice 0)
__device__ __nv_bfloat16 g_ahi[3*MTOT*D_MODEL];
__device__ __nv_bfloat16 g_alo[3*MTOT*D_MODEL];
// weights: 4 slices (wq, wk, wv, wo)
__device__ __nv_bfloat16 g_whi[4*D_MODEL*D_MODEL];
__device__ __nv_bfloat16 g_wlo[4*D_MODEL*D_MODEL];

// Q/K/V in (b,h,t,d) layout, bf16 hi/lo pairs
__device__ __nv_bfloat16 g_Qhi[BB*NH*TT*HD];
__device__ __nv_bfloat16 g_Qlo[BB*NH*TT*HD];
__device__ __nv_bfloat16 g_Khi[BB*NH*TT*HD];
__device__ __nv_bfloat16 g_Klo[BB*NH*TT*HD];
__device__ __nv_bfloat16 g_Vhi[BB*NH*TT*HD];
__device__ __nv_bfloat16 g_Vlo[BB*NH*TT*HD];

// mask block flags: [b][qt][kt] over 128x128 blocks, 1 = fully unmasked
__device__ int g_mflag[BB*16*16];

// ===========================================================================
// helpers
// ===========================================================================
__device__ __forceinline__ uint32_t smem_u32(const void* p) {
    uint32_t a;
    asm("{ .reg .u64 t; cvta.to.shared.u64 t, %1; cvt.u32.u64 %0, t; }"
        : "=r"(a) : "l"(p));
    return a;
}

__device__ __forceinline__ void cvt_split(float4 v, uint2& hi, uint2& lo) {
    __nv_bfloat162 h01 = __floats2bfloat162_rn(v.x, v.y);
    __nv_bfloat162 h23 = __floats2bfloat162_rn(v.z, v.w);
    float r0 = v.x - __bfloat162float(__low2bfloat16(h01));
    float r1 = v.y - __bfloat162float(__high2bfloat16(h01));
    float r2 = v.z - __bfloat162float(__low2bfloat16(h23));
    float r3 = v.w - __bfloat162float(__high2bfloat16(h23));
    __nv_bfloat162 l01 = __floats2bfloat162_rn(r0, r1);
    __nv_bfloat162 l23 = __floats2bfloat162_rn(r2, r3);
    hi.x = *(uint32_t*)&h01; hi.y = *(uint32_t*)&h23;
    lo.x = *(uint32_t*)&l01; lo.y = *(uint32_t*)&l23;
}

__device__ __forceinline__ void cvt2(float a, float b, uint32_t& hi, uint32_t& lo) {
    __nv_bfloat162 h = __floats2bfloat162_rn(a, b);
    float ra = a - __bfloat162float(__low2bfloat16(h));
    float rb = b - __bfloat162float(__high2bfloat16(h));
    __nv_bfloat162 l = __floats2bfloat162_rn(ra, rb);
    hi = *(uint32_t*)&h; lo = *(uint32_t*)&l;
}

#define LDMX4(r, addr) \
    asm volatile("ldmatrix.sync.aligned.m8n8.x4.shared.b16 {%0,%1,%2,%3}, [%4];" \
        : "=r"((r)[0]), "=r"((r)[1]), "=r"((r)[2]), "=r"((r)[3]) : "r"(addr))

#define LDMX4T(r, addr) \
    asm volatile("ldmatrix.sync.aligned.m8n8.x4.trans.shared.b16 {%0,%1,%2,%3}, [%4];" \
        : "=r"((r)[0]), "=r"((r)[1]), "=r"((r)[2]), "=r"((r)[3]) : "r"(addr))

#define MMA16816(c, a, b) \
    asm volatile("mma.sync.aligned.m16n8k16.row.col.f32.bf16.bf16.f32 " \
        "{%0,%1,%2,%3}, {%4,%5,%6,%7}, {%8,%9}, {%0,%1,%2,%3};" \
        : "+f"((c)[0]), "+f"((c)[1]), "+f"((c)[2]), "+f"((c)[3]) \
        : "r"((a)[0]), "r"((a)[1]), "r"((a)[2]), "r"((a)[3]), \
          "r"((b)[0]), "r"((b)[1]))

#define CP_ASYNC16(dst, src) \
    asm volatile("cp.async.cg.shared.global [%0], [%1], 16;" \
        :: "r"(dst), "l"(src))
#define CP_COMMIT() asm volatile("cp.async.commit_group;" ::: "memory")
#define CP_WAIT1()  asm volatile("cp.async.wait_group 1;" ::: "memory")
#define CP_WAIT0()  asm volatile("cp.async.wait_group 0;" ::: "memory")

// ===========================================================================
// Split kernels
// ===========================================================================
__global__ void __launch_bounds__(256) split_a3(
    const float* __restrict__ q, const float* __restrict__ k,
    const float* __restrict__ v)
{
    int z = blockIdx.y;
    int i = blockIdx.x * 256 + threadIdx.x;
    const float* src = (z == 0) ? q : (z == 1) ? k : v;
    float4 val = ((const float4*)src)[i];
    uint2 hi, lo;
    cvt_split(val, hi, lo);
    size_t off = (size_t)z * (MTOT * D_MODEL / 4) + i;
    ((uint2*)g_ahi)[off] = hi;
    ((uint2*)g_alo)[off] = lo;
}

__global__ void __launch_bounds__(256) split_w4(
    const float* __restrict__ wq, const float* __restrict__ wk,
    const float* __restrict__ wv, const float* __restrict__ wo)
{
    int z = blockIdx.y;
    int i = blockIdx.x * 256 + threadIdx.x;
    const float* src = (z == 0) ? wq : (z == 1) ? wk : (z == 2) ? wv : wo;
    float4 v = ((const float4*)src)[i];
    uint2 hi, lo;
    cvt_split(v, hi, lo);
    size_t off = (size_t)z * (D_MODEL * D_MODEL / 4) + i;
    ((uint2*)g_whi)[off] = hi;
    ((uint2*)g_wlo)[off] = lo;
}

// ===========================================================================
// Mask block flags (128x128 blocks)
// ===========================================================================
__global__ void __launch_bounds__(256) mask_flags(const int* __restrict__ mask)
{
    int qt = blockIdx.x, kt = blockIdx.y, b = blockIdx.z;
    int t = threadIdx.x;
    const int* mp = mask + ((size_t)b * TT + qt * 128) * TT + kt * 128;
    int row = t >> 1, ch = (t & 1) * 64;
    bool ok = true;
    #pragma unroll
    for (int i = 0; i < 16; i++) {
        int4 v = *(const int4*)(mp + (size_t)row * TT + ch + i * 4);
        ok = ok && v.x && v.y && v.z && v.w;
    }
    int all = __syncthreads_and((int)ok);
    if (t == 0) g_mflag[(b * 16 + qt) * 16 + kt] = all;
}

// ===========================================================================
// HMMA GEMM with bf16 split. MMA issue order interleaves the 4 acc columns
// per A-fragment (distance-4 RAW chains; per-acc term order unchanged).
// ===========================================================================
#define LDSB 80
#define TILE_B (128*LDSB)
#define STAGE_B (4*TILE_B)
#define GEMM_SMEM (2*STAGE_B)    // 81920 B

#define GEMM_LOAD(kc, stg) do {                                               \
    uint32_t sb0 = smb + (stg) * STAGE_B + tile * TILE_B;                     \
    _Pragma("unroll")                                                         \
    for (int j = 0; j < 8; j++) {                                             \
        int rem = ltid + j * 64;                                              \
        int row = rem >> 2, cc = rem & 3;                                     \
        const __nv_bfloat16* gp =                                             \
            lsrc + (size_t)(grow0 + row) * D_MODEL + (kc) * 32 + cc * 8;      \
        uint32_t dst = sb0 + row * LDSB + cc * 16;                            \
        CP_ASYNC16(dst, gp);                                                  \
    }                                                                         \
    CP_COMMIT();                                                              \
} while (0)

// Shared GEMM mainloop body (acc in caller scope)
#define GEMM_MAIN()                                                           \
    uint32_t arow = warp_m * 64 + (lane & 7) + ((lane >> 3) & 1) * 8;         \
    uint32_t acol = ((lane >> 4) & 1) * 16;                                   \
    uint32_t brow2 = warp_n * 32 + ((lane >> 4) & 1) * 8 + (lane & 7);        \
    uint32_t bcol2 = ((lane >> 3) & 1) * 16;                                  \
    GEMM_LOAD(0, 0);                                                          \
    for (int kc = 0; kc < D_MODEL / 32; kc++) {                               \
        if (kc + 1 < D_MODEL / 32) {                                          \
            GEMM_LOAD(kc + 1, (kc + 1) & 1);                                  \
            CP_WAIT1();                                                       \
        } else {                                                              \
            CP_WAIT0();                                                       \
        }                                                                     \
        __syncthreads();                                                      \
        uint32_t sb = smb + (kc & 1) * STAGE_B;                               \
        uint32_t abase = sb + arow * LDSB + acol;                             \
        uint32_t bbase = sb + 2 * TILE_B + brow2 * LDSB + bcol2;              \
        _Pragma("unroll")                                                     \
        for (int s = 0; s < 2; s++) {                                         \
            uint32_t bh4[2][4], bl4[2][4];                                    \
            _Pragma("unroll")                                                 \
            for (int jp = 0; jp < 2; jp++) {                                  \
                uint32_t ad = bbase + jp * 16 * LDSB + s * 32;                \
                LDMX4(bh4[jp], ad);                                           \
                LDMX4(bl4[jp], ad + TILE_B);                                  \
            }                                                                 \
            _Pragma("unroll")                                                 \
            for (int im = 0; im < 4; im++) {                                  \
                uint32_t ah[4], al[4];                                        \
                uint32_t ad = abase + im * 16 * LDSB + s * 32;                \
                LDMX4(ah, ad);                                                \
                LDMX4(al, ad + TILE_B);                                       \
                /* term 0: ah x bh — sweep all 4 acc columns */               \
                MMA16816(acc[im][0], ah, &bh4[0][0]);                         \
                MMA16816(acc[im][1], ah, &bh4[0][2]);                         \
                MMA16816(acc[im][2], ah, &bh4[1][0]);                         \
                MMA16816(acc[im][3], ah, &bh4[1][2]);                         \
                /* term 1: ah x bl */                                         \
                MMA16816(acc[im][0], ah, &bl4[0][0]);                         \
                MMA16816(acc[im][1], ah, &bl4[0][2]);                         \
                MMA16816(acc[im][2], ah, &bl4[1][0]);                         \
                MMA16816(acc[im][3], ah, &bl4[1][2]);                         \
                /* term 2: al x bh */                                         \
                MMA16816(acc[im][0], al, &bh4[0][0]);                         \
                MMA16816(acc[im][1], al, &bh4[0][2]);                         \
                MMA16816(acc[im][2], al, &bh4[1][0]);                         \
                MMA16816(acc[im][3], al, &bh4[1][2]);                         \
            }                                                                 \
        }                                                                     \
        __syncthreads();                                                      \
    }

// QKV fused: grid (8, 32, 3)
__global__ void __launch_bounds__(256, 2) tc_gemm_qkv(
    const float* __restrict__ bq, const float* __restrict__ bk,
    const float* __restrict__ bv)
{
    extern __shared__ char smc[];
    uint32_t smb = smem_u32(smc);
    int tid = threadIdx.x;
    int lane = tid & 31;
    int wid = tid >> 5;
    int warp_m = wid & 1;
    int warp_n = wid >> 1;
    int m0 = blockIdx.y * 128;
    int n0 = blockIdx.x * 128;
    int z = blockIdx.z;
    const float* bias = (z == 0) ? bq : (z == 1) ? bk : bv;

    int tile = tid >> 6;
    int ltid = tid & 63;
    const __nv_bfloat16* lsrc =
        (tile == 0) ? g_ahi + (size_t)z * MTOT * D_MODEL
      : (tile == 1) ? g_alo + (size_t)z * MTOT * D_MODEL
      : (tile == 2) ? g_whi + (size_t)z * D_MODEL * D_MODEL
                    : g_wlo + (size_t)z * D_MODEL * D_MODEL;
    int grow0 = (tile < 2) ? m0 : n0;

    float acc[4][4][4];
    #pragma unroll
    for (int i = 0; i < 4; i++)
        #pragma unroll
        for (int j = 0; j < 4; j++)
            #pragma unroll
            for (int r = 0; r < 4; r++)
                acc[i][j][r] = 0.f;

    GEMM_MAIN();

    __nv_bfloat16* dhi = (z == 0) ? g_Qhi : (z == 1) ? g_Khi : g_Vhi;
    __nv_bfloat16* dlo = (z == 0) ? g_Qlo : (z == 1) ? g_Klo : g_Vlo;
    #pragma unroll
    for (int im = 0; im < 4; im++) {
        #pragma unroll
        for (int jn = 0; jn < 4; jn++) {
            int m = m0 + warp_m * 64 + im * 16 + (lane >> 2);
            int n = n0 + warp_n * 32 + jn * 8 + (lane & 3) * 2;
            float2 bv2 = *(const float2*)&bias[n];
            float2 v01 = make_float2(acc[im][jn][0] + bv2.x, acc[im][jn][1] + bv2.y);
            float2 v23 = make_float2(acc[im][jn][2] + bv2.x, acc[im][jn][3] + bv2.y);
            int h = n >> 6, d = n & 63;
            int b = m >> 11, t = m & 2047;
            size_t off = (((size_t)b * NH + h) * TT + t) * HD + d;
            uint32_t hi0, lo0, hi1, lo1;
            cvt2(v01.x, v01.y, hi0, lo0);
            cvt2(v23.x, v23.y, hi1, lo1);
            *(uint32_t*)(dhi + off) = hi0;
            *(uint32_t*)(dlo + off) = lo0;
            *(uint32_t*)(dhi + off + 8 * HD) = hi1;
            *(uint32_t*)(dlo + off + 8 * HD) = lo1;
        }
    }
}

// Output projection: A slice 0, W slice 3, flat fp32 out
__global__ void __launch_bounds__(256, 2) tc_gemm_o(
    const float* __restrict__ bias, float* __restrict__ Cflat)
{
    extern __shared__ char smc[];
    uint32_t smb = smem_u32(smc);
    int tid = threadIdx.x;
    int lane = tid & 31;
    int wid = tid >> 5;
    int warp_m = wid & 1;
    int warp_n = wid >> 1;
    int m0 = blockIdx.y * 128;
    int n0 = blockIdx.x * 128;

    int tile = tid >> 6;
    int ltid = tid & 63;
    const __nv_bfloat16* lsrc =
        (tile == 0) ? g_ahi
      : (tile == 1) ? g_alo
      : (tile == 2) ? g_whi + (size_t)3 * D_MODEL * D_MODEL
                    : g_wlo + (size_t)3 * D_MODEL * D_MODEL;
    int grow0 = (tile < 2) ? m0 : n0;

    float acc[4][4][4];
    #pragma unroll
    for (int i = 0; i < 4; i++)
        #pragma unroll
        for (int j = 0; j < 4; j++)
            #pragma unroll
            for (int r = 0; r < 4; r++)
                acc[i][j][r] = 0.f;

    GEMM_MAIN();

    #pragma unroll
    for (int im = 0; im < 4; im++) {
        #pragma unroll
        for (int jn = 0; jn < 4; jn++) {
            int m = m0 + warp_m * 64 + im * 16 + (lane >> 2);
            int n = n0 + warp_n * 32 + jn * 8 + (lane & 3) * 2;
            float2 bv2 = *(const float2*)&bias[n];
            *(float2*)(Cflat + (size_t)m * D_MODEL + n) =
                make_float2(acc[im][jn][0] + bv2.x, acc[im][jn][1] + bv2.y);
            *(float2*)(Cflat + (size_t)(m + 8) * D_MODEL + n) =
                make_float2(acc[im][jn][2] + bv2.x, acc[im][jn][3] + bv2.y);
        }
    }
}

// ===========================================================================
// HMMA flash attention, 64-key tiles, 2 CTAs/SM.
// QK^T and PV process nf-tiles in PAIRS with interleaved MMA issue
// (distance-2 RAW chains; per-acc term order unchanged -> bitwise identical).
// ===========================================================================
#define KVR 64                     // keys per stage
#define KVT (KVR*144)              // 9216 B per tensor tile
#define KVSTG (4*KVT)              // 36864 (Khi,Klo,Vhi,Vlo)
#define QTB 18432                  // Q tile (128 x 144)
#define F_QHI (2*KVSTG)            // 73728
#define F_QLO (F_QHI + QTB)
#define FLASH_SMEM (F_QLO + QTB)   // 110592 B

__global__ void __launch_bounds__(256, 2) flash_attn(const int* __restrict__ mask)
{
    extern __shared__ char smc[];
    uint32_t smb = smem_u32(smc);
    int tid = threadIdx.x;
    int lane = tid & 31;
    int wid = tid >> 5;

    int bh = blockIdx.y;
    int b = bh >> 4;
    int h = bh & 15;
    int q0 = blockIdx.x * 128;

    // stage Q (hi+lo) once
    #pragma unroll
    for (int i = 0; i < 8; i++) {
        int c = tid + i * 256;
        int tens = c >> 10, c2 = c & 1023;
        int row = c2 >> 3, ch = c2 & 7;
        const __nv_bfloat16* src = (tens ? g_Qlo : g_Qhi)
            + ((size_t)bh * TT + q0 + row) * HD + ch * 8;
        CP_ASYNC16(smb + F_QHI + tens * QTB + row * 144 + ch * 16, src);
    }
    CP_COMMIT();

    int ltile = tid >> 6;
    int ltid = tid & 63;
    const __nv_bfloat16* lsrc0 =
        ((ltile == 0) ? g_Khi : (ltile == 1) ? g_Klo
                      : (ltile == 2) ? g_Vhi : g_Vlo) + (size_t)bh * TT * HD;

#define LOAD_KV(j0, stg) do {                                                 \
    const __nv_bfloat16* src = lsrc0 + (size_t)(j0) * HD;                     \
    uint32_t dstb = smb + (stg) * KVSTG + ltile * KVT;                        \
    _Pragma("unroll")                                                         \
    for (int i = 0; i < 8; i++) {                                             \
        int c = ltid + i * 64;                                                \
        int row = c >> 3, ch = c & 7;                                         \
        CP_ASYNC16(dstb + row * 144 + ch * 16, src + row * HD + ch * 8);      \
    }                                                                         \
    CP_COMMIT();                                                              \
} while (0)

    LOAD_KV(0, 0);

    int rowA = q0 + wid * 16 + (lane >> 2);
    const int* m1 = mask + (size_t)b * TT * TT + (size_t)rowA * TT;
    const int* m2 = m1 + 8 * (size_t)TT;
    const int* fl = g_mflag + (b * 16 + blockIdx.x) * 16;

    float o[8][4];
    #pragma unroll
    for (int i = 0; i < 8; i++)
        #pragma unroll
        for (int r = 0; r < 4; r++) o[i][r] = 0.f;
    float mA = -1e30f, mB = -1e30f, lA = 0.f, lB = 0.f;

    uint32_t qbase = smb + F_QHI
        + (wid * 16 + (lane & 7) + ((lane >> 3) & 1) * 8) * 144
        + ((lane >> 4) & 1) * 16;

    for (int jt = 0; jt < TT / KVR; jt++) {
        if (jt + 1 < TT / KVR) {
            LOAD_KV((jt + 1) * KVR, (jt + 1) & 1);
            CP_WAIT1();
        } else {
            CP_WAIT0();
        }
        __syncthreads();

        uint32_t sK = smb + (jt & 1) * KVSTG;
        uint32_t sV = sK + 2 * KVT;

        // ---- S = Q K^T  (16x64 per warp), nf pairs interleaved ----
        float s[8][4];
        #pragma unroll
        for (int i = 0; i < 8; i++)
            #pragma unroll
            for (int r = 0; r < 4; r++) s[i][r] = 0.f;

        #pragma unroll
        for (int ksp = 0; ksp < 2; ksp++) {
            uint32_t ah0[4], ah1[4], al0[4], al1[4];
            uint32_t qa = qbase + ksp * 64;
            LDMX4(ah0, qa);
            LDMX4(ah1, qa + 32);
            LDMX4(al0, qa + QTB);
            LDMX4(al1, qa + QTB + 32);
            #pragma unroll
            for (int np = 0; np < 4; np++) {
                int n0i = 2 * np, n1i = 2 * np + 1;
                uint32_t kb0[4], kl0[4], kb1[4], kl1[4];
                uint32_t ka0 = sK + (n0i * 8 + (lane & 7)) * 144
                             + ksp * 64 + (lane >> 3) * 16;
                uint32_t ka1 = ka0 + 8 * 144;
                LDMX4(kb0, ka0);
                LDMX4(kl0, ka0 + KVT);
                LDMX4(kb1, ka1);
                LDMX4(kl1, ka1 + KVT);
                MMA16816(s[n0i], ah0, &kb0[0]);
                MMA16816(s[n1i], ah0, &kb1[0]);
                MMA16816(s[n0i], ah0, &kl0[0]);
                MMA16816(s[n1i], ah0, &kl1[0]);
                MMA16816(s[n0i], al0, &kb0[0]);
                MMA16816(s[n1i], al0, &kb1[0]);
                MMA16816(s[n0i], ah1, &kb0[2]);
                MMA16816(s[n1i], ah1, &kb1[2]);
                MMA16816(s[n0i], ah1, &kl0[2]);
                MMA16816(s[n1i], ah1, &kl1[2]);
                MMA16816(s[n0i], al1, &kb0[2]);
                MMA16816(s[n1i], al1, &kb1[2]);
            }
        }

        // ---- scale + mask (block-flag fast path) ----
        if (fl[jt >> 1]) {
            #pragma unroll
            for (int nf = 0; nf < 8; nf++) {
                s[nf][0] *= 0.125f; s[nf][1] *= 0.125f;
                s[nf][2] *= 0.125f; s[nf][3] *= 0.125f;
            }
        } else {
            int j0 = jt * KVR;
            #pragma unroll
            for (int nf = 0; nf < 8; nf++) {
                int jc = j0 + nf * 8 + 2 * (lane & 3);
                int2 ma = *(const int2*)(m1 + jc);
                int2 mb = *(const int2*)(m2 + jc);
                s[nf][0] = (ma.x == 0) ? -1e30f : s[nf][0] * 0.125f;
                s[nf][1] = (ma.y == 0) ? -1e30f : s[nf][1] * 0.125f;
                s[nf][2] = (mb.x == 0) ? -1e30f : s[nf][2] * 0.125f;
                s[nf][3] = (mb.y == 0) ? -1e30f : s[nf][3] * 0.125f;
            }
        }

        // ---- online softmax ----
        float tmA = -1e30f, tmB = -1e30f;
        #pragma unroll
        for (int nf = 0; nf < 8; nf++) {
            tmA = fmaxf(tmA, fmaxf(s[nf][0], s[nf][1]));
            tmB = fmaxf(tmB, fmaxf(s[nf][2], s[nf][3]));
        }
        #pragma unroll
        for (int off = 1; off <= 2; off <<= 1) {
            tmA = fmaxf(tmA, __shfl_xor_sync(0xffffffffu, tmA, off));
            tmB = fmaxf(tmB, __shfl_xor_sync(0xffffffffu, tmB, off));
        }
        float mnA = fmaxf(mA, tmA), mnB = fmaxf(mB, tmB);
        float aA = __expf(mA - mnA), aB = __expf(mB - mnB);
        mA = mnA; mB = mnB;

        float tsA = 0.f, tsB = 0.f;
        #pragma unroll
        for (int nf = 0; nf < 8; nf++) {
            s[nf][0] = __expf(s[nf][0] - mA);
            s[nf][1] = __expf(s[nf][1] - mA);
            s[nf][2] = __expf(s[nf][2] - mB);
            s[nf][3] = __expf(s[nf][3] - mB);
            tsA += s[nf][0] + s[nf][1];
            tsB += s[nf][2] + s[nf][3];
        }
        #pragma unroll
        for (int off = 1; off <= 2; off <<= 1) {
            tsA += __shfl_xor_sync(0xffffffffu, tsA, off);
            tsB += __shfl_xor_sync(0xffffffffu, tsB, off);
        }
        lA = lA * aA + tsA;
        lB = lB * aB + tsB;
        #pragma unroll
        for (int nf = 0; nf < 8; nf++) {
            o[nf][0] *= aA; o[nf][1] *= aA;
            o[nf][2] *= aB; o[nf][3] *= aB;
        }

        // ---- O += P V  (nf pairs interleaved) ----
        #pragma unroll
        for (int ksp = 0; ksp < 2; ksp++) {
            uint32_t pah0[4], pal0[4], pah1[4], pal1[4];
            cvt2(s[4*ksp+0][0], s[4*ksp+0][1], pah0[0], pal0[0]);
            cvt2(s[4*ksp+0][2], s[4*ksp+0][3], pah0[1], pal0[1]);
            cvt2(s[4*ksp+1][0], s[4*ksp+1][1], pah0[2], pal0[2]);
            cvt2(s[4*ksp+1][2], s[4*ksp+1][3], pah0[3], pal0[3]);
            cvt2(s[4*ksp+2][0], s[4*ksp+2][1], pah1[0], pal1[0]);
            cvt2(s[4*ksp+2][2], s[4*ksp+2][3], pah1[1], pal1[1]);
            cvt2(s[4*ksp+3][0], s[4*ksp+3][1], pah1[2], pal1[2]);
            cvt2(s[4*ksp+3][2], s[4*ksp+3][3], pah1[3], pal1[3]);
            #pragma unroll
            for (int np = 0; np < 4; np++) {
                int n0i = 2 * np, n1i = 2 * np + 1;
                uint32_t vh0[4], vl0[4], vh1[4], vl1[4];
                uint32_t va0 = sV + (ksp * 32 + lane) * 144 + n0i * 16;
                uint32_t va1 = va0 + 16;
                LDMX4T(vh0, va0);
                LDMX4T(vl0, va0 + KVT);
                LDMX4T(vh1, va1);
                LDMX4T(vl1, va1 + KVT);
                MMA16816(o[n0i], pah0, &vh0[0]);
                MMA16816(o[n1i], pah0, &vh1[0]);
                MMA16816(o[n0i], pah0, &vl0[0]);
                MMA16816(o[n1i], pah0, &vl1[0]);
                MMA16816(o[n0i], pal0, &vh0[0]);
                MMA16816(o[n1i], pal0, &vh1[0]);
                MMA16816(o[n0i], pah1, &vh0[2]);
                MMA16816(o[n1i], pah1, &vh1[2]);
                MMA16816(o[n0i], pah1, &vl0[2]);
                MMA16816(o[n1i], pah1, &vl1[2]);
                MMA16816(o[n0i], pal1, &vh0[2]);
                MMA16816(o[n1i], pal1, &vh1[2]);
            }
        }
        __syncthreads();
    }

    // ---- epilogue: normalize, split to bf16 hi/lo in activation slice 0 ----
    float invA = 1.0f / lA, invB = 1.0f / lB;
    size_t base = ((size_t)b * TT + rowA) * D_MODEL + h * HD + 2 * (lane & 3);
    #pragma unroll
    for (int nf = 0; nf < 8; nf++) {
        uint32_t hi, lo;
        cvt2(o[nf][0] * invA, o[nf][1] * invA, hi, lo);
        *(uint32_t*)(g_ahi + base + nf * 8) = hi;
        *(uint32_t*)(g_alo + base + nf * 8) = lo;
        cvt2(o[nf][2] * invB, o[nf][3] * invB, hi, lo);
        *(uint32_t*)(g_ahi + base + 8 * D_MODEL + nf * 8) = hi;
        *(uint32_t*)(g_alo + base + 8 * D_MODEL + nf * 8) = lo;
    }
#undef LOAD_KV
}

// ---------------------------------------------------------------------------
extern "C" void kernel_launch(void* const* d_in, const int* in_sizes, int n_in,
                              void* d_out, int out_size)
{
    const float* query = (const float*)d_in[0];
    const float* key   = (const float*)d_in[1];
    const float* value = (const float*)d_in[2];
    const int*   mask  = (const int*)d_in[3];
    const float* wq = (const float*)d_in[4];
    const float* bq = (const float*)d_in[5];
    const float* wk = (const float*)d_in[6];
    const float* bk = (const float*)d_in[7];
    const float* wv = (const float*)d_in[8];
    const float* bv = (const float*)d_in[9];
    const float* wo = (const float*)d_in[10];
    const float* bo = (const float*)d_in[11];
    float* out = (float*)d_out;

    cudaFuncSetAttribute(tc_gemm_qkv,
                         cudaFuncAttributeMaxDynamicSharedMemorySize, GEMM_SMEM);
    cudaFuncSetAttribute(tc_gemm_o,
                         cudaFuncAttributeMaxDynamicSharedMemorySize, GEMM_SMEM);
    cudaFuncSetAttribute(flash_attn,
                         cudaFuncAttributeMaxDynamicSharedMemorySize, FLASH_SMEM);

    const int ACT4 = MTOT * D_MODEL / 4;     // 1048576
    const int W4   = D_MODEL * D_MODEL / 4;  // 262144

    split_w4<<<dim3(W4 / 256, 4), 256>>>(wq, wk, wv, wo);
    split_a3<<<dim3(ACT4 / 256, 3), 256>>>(query, key, value);
    mask_flags<<<dim3(16, 16, 2), 256>>>(mask);

    tc_gemm_qkv<<<dim3(8, 32, 3), 256, GEMM_SMEM>>>(bq, bk, bv);

    flash_attn<<<dim3(TT / 128, BB * NH), 256, FLASH_SMEM>>>(mask);

    tc_gemm_o<<<dim3(8, 32), 256, GEMM_SMEM>>>(bo, out);
}

// round 13
// speedup vs baseline: 1.5631x; 1.5631x over previous
#include <cuda_runtime.h>
#include <cuda_bf16.h>
#include <cstdint>

#define D_MODEL 1024
#define NH 16
#define HD 64
#define BB 2
#define TT 2048
#define MTOT (BB*TT)   // 4096

// bf16 hi/lo split scratch: activations 3 slices (q,k,v; att reuses slice 0)
__device__ __nv_bfloat16 g_ahi[3*MTOT*D_MODEL];
__device__ __nv_bfloat16 g_alo[3*MTOT*D_MODEL];
// weights: 4 slices (wq, wk, wv, wo)
__device__ __nv_bfloat16 g_whi[4*D_MODEL*D_MODEL];
__device__ __nv_bfloat16 g_wlo[4*D_MODEL*D_MODEL];

// Q/K/V in (b,h,t,d) layout, bf16 hi/lo pairs
__device__ __nv_bfloat16 g_Qhi[BB*NH*TT*HD];
__device__ __nv_bfloat16 g_Qlo[BB*NH*TT*HD];
__device__ __nv_bfloat16 g_Khi[BB*NH*TT*HD];
__device__ __nv_bfloat16 g_Klo[BB*NH*TT*HD];
__device__ __nv_bfloat16 g_Vhi[BB*NH*TT*HD];
__device__ __nv_bfloat16 g_Vlo[BB*NH*TT*HD];

// mask block flags: [b][qt][kt] over 128x128 blocks, 1 = fully unmasked
__device__ int g_mflag[BB*16*16];

// ===========================================================================
// helpers
// ===========================================================================
__device__ __forceinline__ uint32_t smem_u32(const void* p) {
    uint32_t a;
    asm("{ .reg .u64 t; cvta.to.shared.u64 t, %1; cvt.u32.u64 %0, t; }"
        : "=r"(a) : "l"(p));
    return a;
}

__device__ __forceinline__ void cvt_split(float4 v, uint2& hi, uint2& lo) {
    __nv_bfloat162 h01 = __floats2bfloat162_rn(v.x, v.y);
    __nv_bfloat162 h23 = __floats2bfloat162_rn(v.z, v.w);
    float r0 = v.x - __bfloat162float(__low2bfloat16(h01));
    float r1 = v.y - __bfloat162float(__high2bfloat16(h01));
    float r2 = v.z - __bfloat162float(__low2bfloat16(h23));
    float r3 = v.w - __bfloat162float(__high2bfloat16(h23));
    __nv_bfloat162 l01 = __floats2bfloat162_rn(r0, r1);
    __nv_bfloat162 l23 = __floats2bfloat162_rn(r2, r3);
    hi.x = *(uint32_t*)&h01; hi.y = *(uint32_t*)&h23;
    lo.x = *(uint32_t*)&l01; lo.y = *(uint32_t*)&l23;
}

__device__ __forceinline__ void cvt2(float a, float b, uint32_t& hi, uint32_t& lo) {
    __nv_bfloat162 h = __floats2bfloat162_rn(a, b);
    float ra = a - __bfloat162float(__low2bfloat16(h));
    float rb = b - __bfloat162float(__high2bfloat16(h));
    __nv_bfloat162 l = __floats2bfloat162_rn(ra, rb);
    hi = *(uint32_t*)&h; lo = *(uint32_t*)&l;
}

#define LDMX4(r, addr) \
    asm volatile("ldmatrix.sync.aligned.m8n8.x4.shared.b16 {%0,%1,%2,%3}, [%4];" \
        : "=r"((r)[0]), "=r"((r)[1]), "=r"((r)[2]), "=r"((r)[3]) : "r"(addr))

#define LDMX4T(r, addr) \
    asm volatile("ldmatrix.sync.aligned.m8n8.x4.trans.shared.b16 {%0,%1,%2,%3}, [%4];" \
        : "=r"((r)[0]), "=r"((r)[1]), "=r"((r)[2]), "=r"((r)[3]) : "r"(addr))

#define MMA16816(c, a, b) \
    asm volatile("mma.sync.aligned.m16n8k16.row.col.f32.bf16.bf16.f32 " \
        "{%0,%1,%2,%3}, {%4,%5,%6,%7}, {%8,%9}, {%0,%1,%2,%3};" \
        : "+f"((c)[0]), "+f"((c)[1]), "+f"((c)[2]), "+f"((c)[3]) \
        : "r"((a)[0]), "r"((a)[1]), "r"((a)[2]), "r"((a)[3]), \
          "r"((b)[0]), "r"((b)[1]))

#define CP_ASYNC16(dst, src) \
    asm volatile("cp.async.cg.shared.global [%0], [%1], 16;" \
        :: "r"(dst), "l"(src))
#define CP_COMMIT() asm volatile("cp.async.commit_group;" ::: "memory")
#define CP_WAIT1()  asm volatile("cp.async.wait_group 1;" ::: "memory")
#define CP_WAIT0()  asm volatile("cp.async.wait_group 0;" ::: "memory")

// ===========================================================================
// Fused prep: weight splits (4 slices) + activation splits (3 slices)
// + mask block flags, one launch.
// Grid layout (1D): [0, 12288)   activation splits (z = bid/4096)
//                   [12288, 16384) weight splits  (z = (bid-12288)/1024)
//                   [16384, 16896) mask flags
// ===========================================================================
#define PREP_ACT_BLKS (3*4096)
#define PREP_W_BLKS   (4*1024)
#define PREP_TOTAL (PREP_ACT_BLKS + PREP_W_BLKS + 512)

__global__ void __launch_bounds__(256) prep_all(
    const float* __restrict__ q, const float* __restrict__ k,
    const float* __restrict__ v,
    const float* __restrict__ wq, const float* __restrict__ wk,
    const float* __restrict__ wv, const float* __restrict__ wo,
    const int* __restrict__ mask)
{
    int bid = blockIdx.x;
    int tid = threadIdx.x;

    if (bid < PREP_ACT_BLKS) {
        int z = bid >> 12;                 // /4096
        int i = (bid & 4095) * 256 + tid;
        const float* src = (z == 0) ? q : (z == 1) ? k : v;
        float4 val = ((const float4*)src)[i];
        uint2 hi, lo;
        cvt_split(val, hi, lo);
        size_t off = (size_t)z * (MTOT * D_MODEL / 4) + i;
        ((uint2*)g_ahi)[off] = hi;
        ((uint2*)g_alo)[off] = lo;
    } else if (bid < PREP_ACT_BLKS + PREP_W_BLKS) {
        int r = bid - PREP_ACT_BLKS;
        int z = r >> 10;                   // /1024
        int i = (r & 1023) * 256 + tid;
        const float* src = (z == 0) ? wq : (z == 1) ? wk : (z == 2) ? wv : wo;
        float4 val = ((const float4*)src)[i];
        uint2 hi, lo;
        cvt_split(val, hi, lo);
        size_t off = (size_t)z * (D_MODEL * D_MODEL / 4) + i;
        ((uint2*)g_whi)[off] = hi;
        ((uint2*)g_wlo)[off] = lo;
    } else {
        int r = bid - PREP_ACT_BLKS - PREP_W_BLKS;   // 0..511
        int qt = r & 15, kt = (r >> 4) & 15, b = r >> 8;
        const int* mp = mask + ((size_t)b * TT + qt * 128) * TT + kt * 128;
        int row = tid >> 1, ch = (tid & 1) * 64;
        bool ok = true;
        #pragma unroll
        for (int i = 0; i < 16; i++) {
            int4 vv = *(const int4*)(mp + (size_t)row * TT + ch + i * 4);
            ok = ok && vv.x && vv.y && vv.z && vv.w;
        }
        int all = __syncthreads_and((int)ok);
        if (tid == 0) g_mflag[(b * 16 + qt) * 16 + kt] = all;
    }
}

// ===========================================================================
// HMMA GEMM with bf16 split (round-9 proven inner loop).
// ===========================================================================
#define LDSB 80
#define TILE_B (128*LDSB)
#define STAGE_B (4*TILE_B)
#define GEMM_SMEM (2*STAGE_B)    // 81920 B

#define GEMM_LOAD(kc, stg) do {                                               \
    uint32_t sb0 = smb + (stg) * STAGE_B + tile * TILE_B;                     \
    _Pragma("unroll")                                                         \
    for (int j = 0; j < 8; j++) {                                             \
        int rem = ltid + j * 64;                                              \
        int row = rem >> 2, cc = rem & 3;                                     \
        const __nv_bfloat16* gp =                                             \
            lsrc + (size_t)(grow0 + row) * D_MODEL + (kc) * 32 + cc * 8;      \
        uint32_t dst = sb0 + row * LDSB + cc * 16;                            \
        CP_ASYNC16(dst, gp);                                                  \
    }                                                                         \
    CP_COMMIT();                                                              \
} while (0)

// Shared GEMM mainloop body (acc in caller scope) — R9 schedule
#define GEMM_MAIN()                                                           \
    uint32_t arow = warp_m * 64 + (lane & 7) + ((lane >> 3) & 1) * 8;         \
    uint32_t acol = ((lane >> 4) & 1) * 16;                                   \
    uint32_t brow2 = warp_n * 32 + ((lane >> 4) & 1) * 8 + (lane & 7);        \
    uint32_t bcol2 = ((lane >> 3) & 1) * 16;                                  \
    GEMM_LOAD(0, 0);                                                          \
    for (int kc = 0; kc < D_MODEL / 32; kc++) {                               \
        if (kc + 1 < D_MODEL / 32) {                                          \
            GEMM_LOAD(kc + 1, (kc + 1) & 1);                                  \
            CP_WAIT1();                                                       \
        } else {                                                              \
            CP_WAIT0();                                                       \
        }                                                                     \
        __syncthreads();                                                      \
        uint32_t sb = smb + (kc & 1) * STAGE_B;                               \
        uint32_t abase = sb + arow * LDSB + acol;                             \
        uint32_t bbase = sb + 2 * TILE_B + brow2 * LDSB + bcol2;              \
        _Pragma("unroll")                                                     \
        for (int s = 0; s < 2; s++) {                                         \
            uint32_t bh4[2][4], bl4[2][4];                                    \
            _Pragma("unroll")                                                 \
            for (int jp = 0; jp < 2; jp++) {                                  \
                uint32_t ad = bbase + jp * 16 * LDSB + s * 32;                \
                LDMX4(bh4[jp], ad);                                           \
                LDMX4(bl4[jp], ad + TILE_B);                                  \
            }                                                                 \
            _Pragma("unroll")                                                 \
            for (int im = 0; im < 4; im++) {                                  \
                uint32_t ah[4], al[4];                                        \
                uint32_t ad = abase + im * 16 * LDSB + s * 32;                \
                LDMX4(ah, ad);                                                \
                LDMX4(al, ad + TILE_B);                                       \
                _Pragma("unroll")                                             \
                for (int jp = 0; jp < 2; jp++) {                              \
                    MMA16816(acc[im][2*jp],   ah, &bh4[jp][0]);               \
                    MMA16816(acc[im][2*jp],   ah, &bl4[jp][0]);               \
                    MMA16816(acc[im][2*jp],   al, &bh4[jp][0]);               \
                    MMA16816(acc[im][2*jp+1], ah, &bh4[jp][2]);               \
                    MMA16816(acc[im][2*jp+1], ah, &bl4[jp][2]);               \
                    MMA16816(acc[im][2*jp+1], al, &bh4[jp][2]);               \
                }                                                             \
            }                                                                 \
        }                                                                     \
        __syncthreads();                                                      \
    }

// QKV fused: grid (8, 32, 3)
__global__ void __launch_bounds__(256, 2) tc_gemm_qkv(
    const float* __restrict__ bq, const float* __restrict__ bk,
    const float* __restrict__ bv)
{
    extern __shared__ char smc[];
    uint32_t smb = smem_u32(smc);
    int tid = threadIdx.x;
    int lane = tid & 31;
    int wid = tid >> 5;
    int warp_m = wid & 1;
    int warp_n = wid >> 1;
    int m0 = blockIdx.y * 128;
    int n0 = blockIdx.x * 128;
    int z = blockIdx.z;
    const float* bias = (z == 0) ? bq : (z == 1) ? bk : bv;

    int tile = tid >> 6;
    int ltid = tid & 63;
    const __nv_bfloat16* lsrc =
        (tile == 0) ? g_ahi + (size_t)z * MTOT * D_MODEL
      : (tile == 1) ? g_alo + (size_t)z * MTOT * D_MODEL
      : (tile == 2) ? g_whi + (size_t)z * D_MODEL * D_MODEL
                    : g_wlo + (size_t)z * D_MODEL * D_MODEL;
    int grow0 = (tile < 2) ? m0 : n0;

    float acc[4][4][4];
    #pragma unroll
    for (int i = 0; i < 4; i++)
        #pragma unroll
        for (int j = 0; j < 4; j++)
            #pragma unroll
            for (int r = 0; r < 4; r++)
                acc[i][j][r] = 0.f;

    GEMM_MAIN();

    __nv_bfloat16* dhi = (z == 0) ? g_Qhi : (z == 1) ? g_Khi : g_Vhi;
    __nv_bfloat16* dlo = (z == 0) ? g_Qlo : (z == 1) ? g_Klo : g_Vlo;
    #pragma unroll
    for (int im = 0; im < 4; im++) {
        #pragma unroll
        for (int jn = 0; jn < 4; jn++) {
            int m = m0 + warp_m * 64 + im * 16 + (lane >> 2);
            int n = n0 + warp_n * 32 + jn * 8 + (lane & 3) * 2;
            float2 bv2 = *(const float2*)&bias[n];
            float2 v01 = make_float2(acc[im][jn][0] + bv2.x, acc[im][jn][1] + bv2.y);
            float2 v23 = make_float2(acc[im][jn][2] + bv2.x, acc[im][jn][3] + bv2.y);
            int h = n >> 6, d = n & 63;
            int b = m >> 11, t = m & 2047;
            size_t off = (((size_t)b * NH + h) * TT + t) * HD + d;
            uint32_t hi0, lo0, hi1, lo1;
            cvt2(v01.x, v01.y, hi0, lo0);
            cvt2(v23.x, v23.y, hi1, lo1);
            *(uint32_t*)(dhi + off) = hi0;
            *(uint32_t*)(dlo + off) = lo0;
            *(uint32_t*)(dhi + off + 8 * HD) = hi1;
            *(uint32_t*)(dlo + off + 8 * HD) = lo1;
        }
    }
}

// Output projection: A slice 0, W slice 3, flat fp32 out
__global__ void __launch_bounds__(256, 2) tc_gemm_o(
    const float* __restrict__ bias, float* __restrict__ Cflat)
{
    extern __shared__ char smc[];
    uint32_t smb = smem_u32(smc);
    int tid = threadIdx.x;
    int lane = tid & 31;
    int wid = tid >> 5;
    int warp_m = wid & 1;
    int warp_n = wid >> 1;
    int m0 = blockIdx.y * 128;
    int n0 = blockIdx.x * 128;

    int tile = tid >> 6;
    int ltid = tid & 63;
    const __nv_bfloat16* lsrc =
        (tile == 0) ? g_ahi
      : (tile == 1) ? g_alo
      : (tile == 2) ? g_whi + (size_t)3 * D_MODEL * D_MODEL
                    : g_wlo + (size_t)3 * D_MODEL * D_MODEL;
    int grow0 = (tile < 2) ? m0 : n0;

    float acc[4][4][4];
    #pragma unroll
    for (int i = 0; i < 4; i++)
        #pragma unroll
        for (int j = 0; j < 4; j++)
            #pragma unroll
            for (int r = 0; r < 4; r++)
                acc[i][j][r] = 0.f;

    GEMM_MAIN();

    #pragma unroll
    for (int im = 0; im < 4; im++) {
        #pragma unroll
        for (int jn = 0; jn < 4; jn++) {
            int m = m0 + warp_m * 64 + im * 16 + (lane >> 2);
            int n = n0 + warp_n * 32 + jn * 8 + (lane & 3) * 2;
            float2 bv2 = *(const float2*)&bias[n];
            *(float2*)(Cflat + (size_t)m * D_MODEL + n) =
                make_float2(acc[im][jn][0] + bv2.x, acc[im][jn][1] + bv2.y);
            *(float2*)(Cflat + (size_t)(m + 8) * D_MODEL + n) =
                make_float2(acc[im][jn][2] + bv2.x, acc[im][jn][3] + bv2.y);
        }
    }
}

// ===========================================================================
// HMMA flash attention, 64-key tiles, 2 CTAs/SM (round-9 proven).
// ===========================================================================
#define KVR 64                     // keys per stage
#define KVT (KVR*144)              // 9216 B per tensor tile
#define KVSTG (4*KVT)              // 36864 (Khi,Klo,Vhi,Vlo)
#define QTB 18432                  // Q tile (128 x 144)
#define F_QHI (2*KVSTG)            // 73728
#define F_QLO (F_QHI + QTB)
#define FLASH_SMEM (F_QLO + QTB)   // 110592 B

__global__ void __launch_bounds__(256, 2) flash_attn(const int* __restrict__ mask)
{
    extern __shared__ char smc[];
    uint32_t smb = smem_u32(smc);
    int tid = threadIdx.x;
    int lane = tid & 31;
    int wid = tid >> 5;

    int bh = blockIdx.y;
    int b = bh >> 4;
    int h = bh & 15;
    int q0 = blockIdx.x * 128;

    // stage Q (hi+lo) once
    #pragma unroll
    for (int i = 0; i < 8; i++) {
        int c = tid + i * 256;
        int tens = c >> 10, c2 = c & 1023;
        int row = c2 >> 3, ch = c2 & 7;
        const __nv_bfloat16* src = (tens ? g_Qlo : g_Qhi)
            + ((size_t)bh * TT + q0 + row) * HD + ch * 8;
        CP_ASYNC16(smb + F_QHI + tens * QTB + row * 144 + ch * 16, src);
    }
    CP_COMMIT();

    int ltile = tid >> 6;
    int ltid = tid & 63;
    const __nv_bfloat16* lsrc0 =
        ((ltile == 0) ? g_Khi : (ltile == 1) ? g_Klo
                      : (ltile == 2) ? g_Vhi : g_Vlo) + (size_t)bh * TT * HD;

#define LOAD_KV(j0, stg) do {                                                 \
    const __nv_bfloat16* src = lsrc0 + (size_t)(j0) * HD;                     \
    uint32_t dstb = smb + (stg) * KVSTG + ltile * KVT;                        \
    _Pragma("unroll")                                                         \
    for (int i = 0; i < 8; i++) {                                             \
        int c = ltid + i * 64;                                                \
        int row = c >> 3, ch = c & 7;                                         \
        CP_ASYNC16(dstb + row * 144 + ch * 16, src + row * HD + ch * 8);      \
    }                                                                         \
    CP_COMMIT();                                                              \
} while (0)

    LOAD_KV(0, 0);

    int rowA = q0 + wid * 16 + (lane >> 2);
    const int* m1 = mask + (size_t)b * TT * TT + (size_t)rowA * TT;
    const int* m2 = m1 + 8 * (size_t)TT;
    const int* fl = g_mflag + (b * 16 + blockIdx.x) * 16;

    float o[8][4];
    #pragma unroll
    for (int i = 0; i < 8; i++)
        #pragma unroll
        for (int r = 0; r < 4; r++) o[i][r] = 0.f;
    float mA = -1e30f, mB = -1e30f, lA = 0.f, lB = 0.f;

    uint32_t qbase = smb + F_QHI
        + (wid * 16 + (lane & 7) + ((lane >> 3) & 1) * 8) * 144
        + ((lane >> 4) & 1) * 16;

    for (int jt = 0; jt < TT / KVR; jt++) {
        if (jt + 1 < TT / KVR) {
            LOAD_KV((jt + 1) * KVR, (jt + 1) & 1);
            CP_WAIT1();
        } else {
            CP_WAIT0();
        }
        __syncthreads();

        uint32_t sK = smb + (jt & 1) * KVSTG;
        uint32_t sV = sK + 2 * KVT;

        // ---- S = Q K^T  (16x64 per warp) ----
        float s[8][4];
        #pragma unroll
        for (int i = 0; i < 8; i++)
            #pragma unroll
            for (int r = 0; r < 4; r++) s[i][r] = 0.f;

        #pragma unroll
        for (int ksp = 0; ksp < 2; ksp++) {
            uint32_t ah0[4], ah1[4], al0[4], al1[4];
            uint32_t qa = qbase + ksp * 64;
            LDMX4(ah0, qa);
            LDMX4(ah1, qa + 32);
            LDMX4(al0, qa + QTB);
            LDMX4(al1, qa + QTB + 32);
            #pragma unroll
            for (int nf = 0; nf < 8; nf++) {
                uint32_t kb[4], kl[4];
                uint32_t ka = sK + (nf * 8 + (lane & 7)) * 144
                            + ksp * 64 + (lane >> 3) * 16;
                LDMX4(kb, ka);
                LDMX4(kl, ka + KVT);
                MMA16816(s[nf], ah0, &kb[0]);
                MMA16816(s[nf], ah0, &kl[0]);
                MMA16816(s[nf], al0, &kb[0]);
                MMA16816(s[nf], ah1, &kb[2]);
                MMA16816(s[nf], ah1, &kl[2]);
                MMA16816(s[nf], al1, &kb[2]);
            }
        }

        // ---- scale + mask (block-flag fast path) ----
        if (fl[jt >> 1]) {
            #pragma unroll
            for (int nf = 0; nf < 8; nf++) {
                s[nf][0] *= 0.125f; s[nf][1] *= 0.125f;
                s[nf][2] *= 0.125f; s[nf][3] *= 0.125f;
            }
        } else {
            int j0 = jt * KVR;
            #pragma unroll
            for (int nf = 0; nf < 8; nf++) {
                int jc = j0 + nf * 8 + 2 * (lane & 3);
                int2 ma = *(const int2*)(m1 + jc);
                int2 mb = *(const int2*)(m2 + jc);
                s[nf][0] = (ma.x == 0) ? -1e30f : s[nf][0] * 0.125f;
                s[nf][1] = (ma.y == 0) ? -1e30f : s[nf][1] * 0.125f;
                s[nf][2] = (mb.x == 0) ? -1e30f : s[nf][2] * 0.125f;
                s[nf][3] = (mb.y == 0) ? -1e30f : s[nf][3] * 0.125f;
            }
        }

        // ---- online softmax ----
        float tmA = -1e30f, tmB = -1e30f;
        #pragma unroll
        for (int nf = 0; nf < 8; nf++) {
            tmA = fmaxf(tmA, fmaxf(s[nf][0], s[nf][1]));
            tmB = fmaxf(tmB, fmaxf(s[nf][2], s[nf][3]));
        }
        #pragma unroll
        for (int off = 1; off <= 2; off <<= 1) {
            tmA = fmaxf(tmA, __shfl_xor_sync(0xffffffffu, tmA, off));
            tmB = fmaxf(tmB, __shfl_xor_sync(0xffffffffu, tmB, off));
        }
        float mnA = fmaxf(mA, tmA), mnB = fmaxf(mB, tmB);
        float aA = __expf(mA - mnA), aB = __expf(mB - mnB);
        mA = mnA; mB = mnB;

        float tsA = 0.f, tsB = 0.f;
        #pragma unroll
        for (int nf = 0; nf < 8; nf++) {
            s[nf][0] = __expf(s[nf][0] - mA);
            s[nf][1] = __expf(s[nf][1] - mA);
            s[nf][2] = __expf(s[nf][2] - mB);
            s[nf][3] = __expf(s[nf][3] - mB);
            tsA += s[nf][0] + s[nf][1];
            tsB += s[nf][2] + s[nf][3];
        }
        #pragma unroll
        for (int off = 1; off <= 2; off <<= 1) {
            tsA += __shfl_xor_sync(0xffffffffu, tsA, off);
            tsB += __shfl_xor_sync(0xffffffffu, tsB, off);
        }
        lA = lA * aA + tsA;
        lB = lB * aB + tsB;
        #pragma unroll
        for (int nf = 0; nf < 8; nf++) {
            o[nf][0] *= aA; o[nf][1] *= aA;
            o[nf][2] *= aB; o[nf][3] *= aB;
        }

        // ---- O += P V ----
        #pragma unroll
        for (int ksp = 0; ksp < 2; ksp++) {
            uint32_t pah0[4], pal0[4], pah1[4], pal1[4];
            cvt2(s[4*ksp+0][0], s[4*ksp+0][1], pah0[0], pal0[0]);
            cvt2(s[4*ksp+0][2], s[4*ksp+0][3], pah0[1], pal0[1]);
            cvt2(s[4*ksp+1][0], s[4*ksp+1][1], pah0[2], pal0[2]);
            cvt2(s[4*ksp+1][2], s[4*ksp+1][3], pah0[3], pal0[3]);
            cvt2(s[4*ksp+2][0], s[4*ksp+2][1], pah1[0], pal1[0]);
            cvt2(s[4*ksp+2][2], s[4*ksp+2][3], pah1[1], pal1[1]);
            cvt2(s[4*ksp+3][0], s[4*ksp+3][1], pah1[2], pal1[2]);
            cvt2(s[4*ksp+3][2], s[4*ksp+3][3], pah1[3], pal1[3]);
            #pragma unroll
            for (int nf = 0; nf < 8; nf++) {
                uint32_t vh[4], vl[4];
                uint32_t va = sV + (ksp * 32 + lane) * 144 + nf * 16;
                LDMX4T(vh, va);
                LDMX4T(vl, va + KVT);
                MMA16816(o[nf], pah0, &vh[0]);
                MMA16816(o[nf], pah0, &vl[0]);
                MMA16816(o[nf], pal0, &vh[0]);
                MMA16816(o[nf], pah1, &vh[2]);
                MMA16816(o[nf], pah1, &vl[2]);
                MMA16816(o[nf], pal1, &vh[2]);
            }
        }
        __syncthreads();
    }

    // ---- epilogue: normalize, split to bf16 hi/lo in activation slice 0 ----
    float invA = 1.0f / lA, invB = 1.0f / lB;
    size_t base = ((size_t)b * TT + rowA) * D_MODEL + h * HD + 2 * (lane & 3);
    #pragma unroll
    for (int nf = 0; nf < 8; nf++) {
        uint32_t hi, lo;
        cvt2(o[nf][0] * invA, o[nf][1] * invA, hi, lo);
        *(uint32_t*)(g_ahi + base + nf * 8) = hi;
        *(uint32_t*)(g_alo + base + nf * 8) = lo;
        cvt2(o[nf][2] * invB, o[nf][3] * invB, hi, lo);
        *(uint32_t*)(g_ahi + base + 8 * D_MODEL + nf * 8) = hi;
        *(uint32_t*)(g_alo + base + 8 * D_MODEL + nf * 8) = lo;
    }
#undef LOAD_KV
}

// ---------------------------------------------------------------------------
extern "C" void kernel_launch(void* const* d_in, const int* in_sizes, int n_in,
                              void* d_out, int out_size)
{
    const float* query = (const float*)d_in[0];
    const float* key   = (const float*)d_in[1];
    const float* value = (const float*)d_in[2];
    const int*   mask  = (const int*)d_in[3];
    const float* wq = (const float*)d_in[4];
    const float* bq = (const float*)d_in[5];
    const float* wk = (const float*)d_in[6];
    const float* bk = (const float*)d_in[7];
    const float* wv = (const float*)d_in[8];
    const float* bv = (const float*)d_in[9];
    const float* wo = (const float*)d_in[10];
    const float* bo = (const float*)d_in[11];
    float* out = (float*)d_out;

    cudaFuncSetAttribute(tc_gemm_qkv,
                         cudaFuncAttributeMaxDynamicSharedMemorySize, GEMM_SMEM);
    cudaFuncSetAttribute(tc_gemm_o,
                         cudaFuncAttributeMaxDynamicSharedMemorySize, GEMM_SMEM);
    cudaFuncSetAttribute(flash_attn,
                         cudaFuncAttributeMaxDynamicSharedMemorySize, FLASH_SMEM);

    prep_all<<<PREP_TOTAL, 256>>>(query, key, value, wq, wk, wv, wo, mask);

    tc_gemm_qkv<<<dim3(8, 32, 3), 256, GEMM_SMEM>>>(bq, bk, bv);

    flash_attn<<<dim3(TT / 128, BB * NH), 256, FLASH_SMEM>>>(mask);

    tc_gemm_o<<<dim3(8, 32), 256, GEMM_SMEM>>>(bo, out);
}

// round 15
// speedup vs baseline: 1.8179x; 1.1630x over previous
#include <cuda_runtime.h>
#include <cuda_fp16.h>
#include <cstdint>

#define D_MODEL 1024
#define NH 16
#define HD 64
#define BB 2
#define TT 2048
#define MTOT (BB*TT)   // 4096

// fp16 hi/lo split scratch: activations 3 slices (q,k,v; att reuses slice 0)
__device__ __half g_ahi[3*MTOT*D_MODEL];
__device__ __half g_alo[3*MTOT*D_MODEL];
// weight hi: 4 slices (wq, wk, wv, wo); weight lo: 2 slices (wv, wo only)
__device__ __half g_whi[4*D_MODEL*D_MODEL];
__device__ __half g_wlo[2*D_MODEL*D_MODEL];

// Q/K/V in (b,h,t,d) layout, fp16. Q needs lo (QK^T cross term),
// K hi-only (2-term QK^T), V hi+lo (3-term PV).
__device__ __half g_Qhi[BB*NH*TT*HD];
__device__ __half g_Qlo[BB*NH*TT*HD];
__device__ __half g_Khi[BB*NH*TT*HD];
__device__ __half g_Vhi[BB*NH*TT*HD];
__device__ __half g_Vlo[BB*NH*TT*HD];

// mask block flags: [b][qt][kt] over 128x128 blocks, 1 = fully unmasked
__device__ int g_mflag[BB*16*16];

// ===========================================================================
// helpers
// ===========================================================================
__device__ __forceinline__ uint32_t smem_u32(const void* p) {
    uint32_t a;
    asm("{ .reg .u64 t; cvta.to.shared.u64 t, %1; cvt.u32.u64 %0, t; }"
        : "=r"(a) : "l"(p));
    return a;
}

__device__ __forceinline__ void cvt_split_h(float4 v, uint2& hi, uint2& lo) {
    __half2 h01 = __floats2half2_rn(v.x, v.y);
    __half2 h23 = __floats2half2_rn(v.z, v.w);
    float r0 = v.x - __low2float(h01);
    float r1 = v.y - __high2float(h01);
    float r2 = v.z - __low2float(h23);
    float r3 = v.w - __high2float(h23);
    __half2 l01 = __floats2half2_rn(r0, r1);
    __half2 l23 = __floats2half2_rn(r2, r3);
    hi.x = *(uint32_t*)&h01; hi.y = *(uint32_t*)&h23;
    lo.x = *(uint32_t*)&l01; lo.y = *(uint32_t*)&l23;
}

__device__ __forceinline__ void cvt2h(float a, float b, uint32_t& hi, uint32_t& lo) {
    __half2 h = __floats2half2_rn(a, b);
    float ra = a - __low2float(h);
    float rb = b - __high2float(h);
    __half2 l = __floats2half2_rn(ra, rb);
    hi = *(uint32_t*)&h; lo = *(uint32_t*)&l;
}

#define LDMX4(r, addr) \
    asm volatile("ldmatrix.sync.aligned.m8n8.x4.shared.b16 {%0,%1,%2,%3}, [%4];" \
        : "=r"((r)[0]), "=r"((r)[1]), "=r"((r)[2]), "=r"((r)[3]) : "r"(addr))

#define LDMX4T(r, addr) \
    asm volatile("ldmatrix.sync.aligned.m8n8.x4.trans.shared.b16 {%0,%1,%2,%3}, [%4];" \
        : "=r"((r)[0]), "=r"((r)[1]), "=r"((r)[2]), "=r"((r)[3]) : "r"(addr))

#define MMA16816(c, a, b) \
    asm volatile("mma.sync.aligned.m16n8k16.row.col.f32.f16.f16.f32 " \
        "{%0,%1,%2,%3}, {%4,%5,%6,%7}, {%8,%9}, {%0,%1,%2,%3};" \
        : "+f"((c)[0]), "+f"((c)[1]), "+f"((c)[2]), "+f"((c)[3]) \
        : "r"((a)[0]), "r"((a)[1]), "r"((a)[2]), "r"((a)[3]), \
          "r"((b)[0]), "r"((b)[1]))

#define CP_ASYNC16(dst, src) \
    asm volatile("cp.async.cg.shared.global [%0], [%1], 16;" \
        :: "r"(dst), "l"(src))
#define CP_COMMIT() asm volatile("cp.async.commit_group;" ::: "memory")
#define CP_WAIT1()  asm volatile("cp.async.wait_group 1;" ::: "memory")
#define CP_WAIT0()  asm volatile("cp.async.wait_group 0;" ::: "memory")

// ===========================================================================
// Fused prep: weight splits + activation splits + mask block flags.
// ===========================================================================
#define PREP_ACT_BLKS (3*4096)
#define PREP_W_BLKS   (4*1024)
#define PREP_TOTAL (PREP_ACT_BLKS + PREP_W_BLKS + 512)

__global__ void __launch_bounds__(256) prep_all(
    const float* __restrict__ q, const float* __restrict__ k,
    const float* __restrict__ v,
    const float* __restrict__ wq, const float* __restrict__ wk,
    const float* __restrict__ wv, const float* __restrict__ wo,
    const int* __restrict__ mask)
{
    int bid = blockIdx.x;
    int tid = threadIdx.x;

    if (bid < PREP_ACT_BLKS) {
        int z = bid >> 12;
        int i = (bid & 4095) * 256 + tid;
        const float* src = (z == 0) ? q : (z == 1) ? k : v;
        float4 val = ((const float4*)src)[i];
        uint2 hi, lo;
        cvt_split_h(val, hi, lo);
        size_t off = (size_t)z * (MTOT * D_MODEL / 4) + i;
        ((uint2*)g_ahi)[off] = hi;
        ((uint2*)g_alo)[off] = lo;
    } else if (bid < PREP_ACT_BLKS + PREP_W_BLKS) {
        int r = bid - PREP_ACT_BLKS;
        int z = r >> 10;
        int i = (r & 1023) * 256 + tid;
        const float* src = (z == 0) ? wq : (z == 1) ? wk : (z == 2) ? wv : wo;
        float4 val = ((const float4*)src)[i];
        uint2 hi, lo;
        cvt_split_h(val, hi, lo);
        ((uint2*)g_whi)[(size_t)z * (D_MODEL * D_MODEL / 4) + i] = hi;
        if (z >= 2)
            ((uint2*)g_wlo)[(size_t)(z - 2) * (D_MODEL * D_MODEL / 4) + i] = lo;
    } else {
        int r = bid - PREP_ACT_BLKS - PREP_W_BLKS;   // 0..511
        int qt = r & 15, kt = (r >> 4) & 15, b = r >> 8;
        const int* mp = mask + ((size_t)b * TT + qt * 128) * TT + kt * 128;
        int row = tid >> 1, ch = (tid & 1) * 64;
        bool ok = true;
        #pragma unroll
        for (int i = 0; i < 16; i++) {
            int4 vv = *(const int4*)(mp + (size_t)row * TT + ch + i * 4);
            ok = ok && vv.x && vv.y && vv.z && vv.w;
        }
        int all = __syncthreads_and((int)ok);
        if (tid == 0) g_mflag[(b * 16 + qt) * 16 + kt] = all;
    }
}

// ===========================================================================
// HMMA GEMM. 3-tile (2-term) and 4-tile (3-term, R9-proven) variants.
// ===========================================================================
#define LDSB 80
#define TILE_B (128*LDSB)
#define STAGE3_B (3*TILE_B)
#define STAGE4_B (4*TILE_B)
#define GEMM3_SMEM (2*STAGE3_B)   // 61440
#define GEMM4_SMEM (2*STAGE4_B)   // 81920

// --- 3-tile loader: Ahi, Alo (64 thr x 8 chunks each), Whi (128 thr x 4) ---
#define GEMM_LOAD3(kc, stg) do {                                              \
    uint32_t sb0 = smb + (stg) * STAGE3_B;                                    \
    if (tid < 128) {                                                          \
        int tl = tid >> 6, lt = tid & 63;                                     \
        const __half* sp = tl ? lsAlo : lsAhi;                                \
        _Pragma("unroll")                                                     \
        for (int j = 0; j < 8; j++) {                                         \
            int rem = lt + j * 64;                                            \
            int row = rem >> 2, cc = rem & 3;                                 \
            CP_ASYNC16(sb0 + tl * TILE_B + row * LDSB + cc * 16,              \
                       sp + (size_t)(m0 + row) * D_MODEL + (kc) * 32 + cc * 8); \
        }                                                                     \
    } else {                                                                  \
        int lt = tid - 128;                                                   \
        _Pragma("unroll")                                                     \
        for (int j = 0; j < 4; j++) {                                         \
            int rem = lt + j * 128;                                           \
            int row = rem >> 2, cc = rem & 3;                                 \
            CP_ASYNC16(sb0 + 2 * TILE_B + row * LDSB + cc * 16,               \
                       lsW + (size_t)(n0 + row) * D_MODEL + (kc) * 32 + cc * 8); \
        }                                                                     \
    }                                                                         \
    CP_COMMIT();                                                              \
} while (0)

#define GEMM_MAIN3()                                                          \
    uint32_t arow = warp_m * 64 + (lane & 7) + ((lane >> 3) & 1) * 8;         \
    uint32_t acol = ((lane >> 4) & 1) * 16;                                   \
    uint32_t brow2 = warp_n * 32 + ((lane >> 4) & 1) * 8 + (lane & 7);        \
    uint32_t bcol2 = ((lane >> 3) & 1) * 16;                                  \
    GEMM_LOAD3(0, 0);                                                         \
    for (int kc = 0; kc < D_MODEL / 32; kc++) {                               \
        if (kc + 1 < D_MODEL / 32) { GEMM_LOAD3(kc + 1, (kc + 1) & 1); CP_WAIT1(); } \
        else { CP_WAIT0(); }                                                  \
        __syncthreads();                                                      \
        uint32_t sb = smb + (kc & 1) * STAGE3_B;                              \
        uint32_t abase = sb + arow * LDSB + acol;                             \
        uint32_t bbase = sb + 2 * TILE_B + brow2 * LDSB + bcol2;              \
        _Pragma("unroll")                                                     \
        for (int s = 0; s < 2; s++) {                                         \
            uint32_t bh4[2][4];                                               \
            _Pragma("unroll")                                                 \
            for (int jp = 0; jp < 2; jp++)                                    \
                LDMX4(bh4[jp], bbase + jp * 16 * LDSB + s * 32);              \
            _Pragma("unroll")                                                 \
            for (int im = 0; im < 4; im++) {                                  \
                uint32_t ah[4], al[4];                                        \
                uint32_t ad = abase + im * 16 * LDSB + s * 32;                \
                LDMX4(ah, ad);                                                \
                LDMX4(al, ad + TILE_B);                                       \
                _Pragma("unroll")                                             \
                for (int jp = 0; jp < 2; jp++) {                              \
                    MMA16816(acc[im][2*jp],   ah, &bh4[jp][0]);               \
                    MMA16816(acc[im][2*jp],   al, &bh4[jp][0]);               \
                    MMA16816(acc[im][2*jp+1], ah, &bh4[jp][2]);               \
                    MMA16816(acc[im][2*jp+1], al, &bh4[jp][2]);               \
                }                                                             \
            }                                                                 \
        }                                                                     \
        __syncthreads();                                                      \
    }

// --- 4-tile loader + mainloop (R9-proven structure) ---
#define GEMM_LOAD4(kc, stg) do {                                              \
    uint32_t sb0 = smb + (stg) * STAGE4_B + tile * TILE_B;                    \
    _Pragma("unroll")                                                         \
    for (int j = 0; j < 8; j++) {                                             \
        int rem = ltid + j * 64;                                              \
        int row = rem >> 2, cc = rem & 3;                                     \
        CP_ASYNC16(sb0 + row * LDSB + cc * 16,                                \
                   lsrc + (size_t)(grow0 + row) * D_MODEL + (kc) * 32 + cc * 8); \
    }                                                                         \
    CP_COMMIT();                                                              \
} while (0)

#define GEMM_MAIN4()                                                          \
    uint32_t arow = warp_m * 64 + (lane & 7) + ((lane >> 3) & 1) * 8;         \
    uint32_t acol = ((lane >> 4) & 1) * 16;                                   \
    uint32_t brow2 = warp_n * 32 + ((lane >> 4) & 1) * 8 + (lane & 7);        \
    uint32_t bcol2 = ((lane >> 3) & 1) * 16;                                  \
    GEMM_LOAD4(0, 0);                                                         \
    for (int kc = 0; kc < D_MODEL / 32; kc++) {                               \
        if (kc + 1 < D_MODEL / 32) { GEMM_LOAD4(kc + 1, (kc + 1) & 1); CP_WAIT1(); } \
        else { CP_WAIT0(); }                                                  \
        __syncthreads();                                                      \
        uint32_t sb = smb + (kc & 1) * STAGE4_B;                              \
        uint32_t abase = sb + arow * LDSB + acol;                             \
        uint32_t bbase = sb + 2 * TILE_B + brow2 * LDSB + bcol2;              \
        _Pragma("unroll")                                                     \
        for (int s = 0; s < 2; s++) {                                         \
            uint32_t bh4[2][4], bl4[2][4];                                    \
            _Pragma("unroll")                                                 \
            for (int jp = 0; jp < 2; jp++) {                                  \
                uint32_t ad = bbase + jp * 16 * LDSB + s * 32;                \
                LDMX4(bh4[jp], ad);                                           \
                LDMX4(bl4[jp], ad + TILE_B);                                  \
            }                                                                 \
            _Pragma("unroll")                                                 \
            for (int im = 0; im < 4; im++) {                                  \
                uint32_t ah[4], al[4];                                        \
                uint32_t ad = abase + im * 16 * LDSB + s * 32;                \
                LDMX4(ah, ad);                                                \
                LDMX4(al, ad + TILE_B);                                       \
                _Pragma("unroll")                                             \
                for (int jp = 0; jp < 2; jp++) {                              \
                    MMA16816(acc[im][2*jp],   ah, &bh4[jp][0]);               \
                    MMA16816(acc[im][2*jp],   ah, &bl4[jp][0]);               \
                    MMA16816(acc[im][2*jp],   al, &bh4[jp][0]);               \
                    MMA16816(acc[im][2*jp+1], ah, &bh4[jp][2]);               \
                    MMA16816(acc[im][2*jp+1], ah, &bl4[jp][2]);               \
                    MMA16816(acc[im][2*jp+1], al, &bh4[jp][2]);               \
                }                                                             \
            }                                                                 \
        }                                                                     \
        __syncthreads();                                                      \
    }

// Q/K projections, 2-term: grid (8, 32, 2)
__global__ void __launch_bounds__(256, 2) tc_gemm_qk(
    const float* __restrict__ bq, const float* __restrict__ bk)
{
    extern __shared__ char smc[];
    uint32_t smb = smem_u32(smc);
    int tid = threadIdx.x;
    int lane = tid & 31;
    int wid = tid >> 5;
    int warp_m = wid & 1;
    int warp_n = wid >> 1;
    int m0 = blockIdx.y * 128;
    int n0 = blockIdx.x * 128;
    int z = blockIdx.z;
    const float* bias = (z == 0) ? bq : bk;

    const __half* lsAhi = g_ahi + (size_t)z * MTOT * D_MODEL;
    const __half* lsAlo = g_alo + (size_t)z * MTOT * D_MODEL;
    const __half* lsW   = g_whi + (size_t)z * D_MODEL * D_MODEL;

    float acc[4][4][4];
    #pragma unroll
    for (int i = 0; i < 4; i++)
        #pragma unroll
        for (int j = 0; j < 4; j++)
            #pragma unroll
            for (int r = 0; r < 4; r++) acc[i][j][r] = 0.f;

    GEMM_MAIN3();

    __half* dhi = (z == 0) ? g_Qhi : g_Khi;
    #pragma unroll
    for (int im = 0; im < 4; im++) {
        #pragma unroll
        for (int jn = 0; jn < 4; jn++) {
            int m = m0 + warp_m * 64 + im * 16 + (lane >> 2);
            int n = n0 + warp_n * 32 + jn * 8 + (lane & 3) * 2;
            float2 bv2 = *(const float2*)&bias[n];
            float2 v01 = make_float2(acc[im][jn][0] + bv2.x, acc[im][jn][1] + bv2.y);
            float2 v23 = make_float2(acc[im][jn][2] + bv2.x, acc[im][jn][3] + bv2.y);
            int h = n >> 6, d = n & 63;
            int b = m >> 11, t = m & 2047;
            size_t off = (((size_t)b * NH + h) * TT + t) * HD + d;
            uint32_t hi0, lo0, hi1, lo1;
            cvt2h(v01.x, v01.y, hi0, lo0);
            cvt2h(v23.x, v23.y, hi1, lo1);
            *(uint32_t*)(dhi + off) = hi0;
            *(uint32_t*)(dhi + off + 8 * HD) = hi1;
            if (z == 0) {
                *(uint32_t*)(g_Qlo + off) = lo0;
                *(uint32_t*)(g_Qlo + off + 8 * HD) = lo1;
            }
        }
    }
}

// V projection, 3-term: grid (8, 32)
__global__ void __launch_bounds__(256, 2) tc_gemm_v(const float* __restrict__ bias)
{
    extern __shared__ char smc[];
    uint32_t smb = smem_u32(smc);
    int tid = threadIdx.x;
    int lane = tid & 31;
    int wid = tid >> 5;
    int warp_m = wid & 1;
    int warp_n = wid >> 1;
    int m0 = blockIdx.y * 128;
    int n0 = blockIdx.x * 128;

    int tile = tid >> 6;
    int ltid = tid & 63;
    const __half* lsrc =
        (tile == 0) ? g_ahi + (size_t)2 * MTOT * D_MODEL
      : (tile == 1) ? g_alo + (size_t)2 * MTOT * D_MODEL
      : (tile == 2) ? g_whi + (size_t)2 * D_MODEL * D_MODEL
                    : g_wlo;                                  // wv_lo = slice 0
    int grow0 = (tile < 2) ? m0 : n0;

    float acc[4][4][4];
    #pragma unroll
    for (int i = 0; i < 4; i++)
        #pragma unroll
        for (int j = 0; j < 4; j++)
            #pragma unroll
            for (int r = 0; r < 4; r++) acc[i][j][r] = 0.f;

    GEMM_MAIN4();

    #pragma unroll
    for (int im = 0; im < 4; im++) {
        #pragma unroll
        for (int jn = 0; jn < 4; jn++) {
            int m = m0 + warp_m * 64 + im * 16 + (lane >> 2);
            int n = n0 + warp_n * 32 + jn * 8 + (lane & 3) * 2;
            float2 bv2 = *(const float2*)&bias[n];
            float2 v01 = make_float2(acc[im][jn][0] + bv2.x, acc[im][jn][1] + bv2.y);
            float2 v23 = make_float2(acc[im][jn][2] + bv2.x, acc[im][jn][3] + bv2.y);
            int h = n >> 6, d = n & 63;
            int b = m >> 11, t = m & 2047;
            size_t off = (((size_t)b * NH + h) * TT + t) * HD + d;
            uint32_t hi0, lo0, hi1, lo1;
            cvt2h(v01.x, v01.y, hi0, lo0);
            cvt2h(v23.x, v23.y, hi1, lo1);
            *(uint32_t*)(g_Vhi + off) = hi0;
            *(uint32_t*)(g_Vlo + off) = lo0;
            *(uint32_t*)(g_Vhi + off + 8 * HD) = hi1;
            *(uint32_t*)(g_Vlo + off + 8 * HD) = lo1;
        }
    }
}

// Output projection, 3-term: grid (8, 32), fp32 flat out
__global__ void __launch_bounds__(256, 2) tc_gemm_o(
    const float* __restrict__ bias, float* __restrict__ Cflat)
{
    extern __shared__ char smc[];
    uint32_t smb = smem_u32(smc);
    int tid = threadIdx.x;
    int lane = tid & 31;
    int wid = tid >> 5;
    int warp_m = wid & 1;
    int warp_n = wid >> 1;
    int m0 = blockIdx.y * 128;
    int n0 = blockIdx.x * 128;

    int tile = tid >> 6;
    int ltid = tid & 63;
    const __half* lsrc =
        (tile == 0) ? g_ahi
      : (tile == 1) ? g_alo
      : (tile == 2) ? g_whi + (size_t)3 * D_MODEL * D_MODEL
                    : g_wlo + (size_t)1 * D_MODEL * D_MODEL;  // wo_lo = slice 1
    int grow0 = (tile < 2) ? m0 : n0;

    float acc[4][4][4];
    #pragma unroll
    for (int i = 0; i < 4; i++)
        #pragma unroll
        for (int j = 0; j < 4; j++)
            #pragma unroll
            for (int r = 0; r < 4; r++) acc[i][j][r] = 0.f;

    GEMM_MAIN4();

    #pragma unroll
    for (int im = 0; im < 4; im++) {
        #pragma unroll
        for (int jn = 0; jn < 4; jn++) {
            int m = m0 + warp_m * 64 + im * 16 + (lane >> 2);
            int n = n0 + warp_n * 32 + jn * 8 + (lane & 3) * 2;
            float2 bv2 = *(const float2*)&bias[n];
            *(float2*)(Cflat + (size_t)m * D_MODEL + n) =
                make_float2(acc[im][jn][0] + bv2.x, acc[im][jn][1] + bv2.y);
            *(float2*)(Cflat + (size_t)(m + 8) * D_MODEL + n) =
                make_float2(acc[im][jn][2] + bv2.x, acc[im][jn][3] + bv2.y);
        }
    }
}

// ===========================================================================
// HMMA flash attention, fp16. QK^T 2-term (Qhi,Qlo x Khi), PV 3-term.
// KV stage = Khi, Vhi, Vlo (3 tiles). 64-key tiles, 2 CTAs/SM.
// ===========================================================================
#define KVR 64
#define KVT (KVR*144)              // 9216
#define KVSTG (3*KVT)              // 27648
#define QTB 18432                  // 128 x 144
#define F_QHI (2*KVSTG)            // 55296
#define F_QLO (F_QHI + QTB)
#define FLASH_SMEM (F_QLO + QTB)   // 92160

__global__ void __launch_bounds__(256, 2) flash_attn(const int* __restrict__ mask)
{
    extern __shared__ char smc[];
    uint32_t smb = smem_u32(smc);
    int tid = threadIdx.x;
    int lane = tid & 31;
    int wid = tid >> 5;

    int bh = blockIdx.y;
    int b = bh >> 4;
    int h = bh & 15;
    int q0 = blockIdx.x * 128;

    // stage Q (hi+lo) once
    #pragma unroll
    for (int i = 0; i < 8; i++) {
        int c = tid + i * 256;
        int tens = c >> 10, c2 = c & 1023;
        int row = c2 >> 3, ch = c2 & 7;
        const __half* src = (tens ? g_Qlo : g_Qhi)
            + ((size_t)bh * TT + q0 + row) * HD + ch * 8;
        CP_ASYNC16(smb + F_QHI + tens * QTB + row * 144 + ch * 16, src);
    }
    CP_COMMIT();

    const __half* kKhi = g_Khi + (size_t)bh * TT * HD;
    const __half* kVhi = g_Vhi + (size_t)bh * TT * HD;
    const __half* kVlo = g_Vlo + (size_t)bh * TT * HD;

#define LOAD_KV(j0, stg) do {                                                 \
    uint32_t dstb = smb + (stg) * KVSTG;                                      \
    _Pragma("unroll")                                                         \
    for (int i = 0; i < 6; i++) {                                             \
        const __half* sp = (i < 2) ? kKhi : (i < 4) ? kVhi : kVlo;            \
        int rem = tid + (i & 1) * 256;                                        \
        int row = rem >> 3, ch = rem & 7;                                     \
        CP_ASYNC16(dstb + (i >> 1) * KVT + row * 144 + ch * 16,               \
                   sp + (size_t)((j0) + row) * HD + ch * 8);                  \
    }                                                                         \
    CP_COMMIT();                                                              \
} while (0)

    LOAD_KV(0, 0);

    int rowA = q0 + wid * 16 + (lane >> 2);
    const int* m1 = mask + (size_t)b * TT * TT + (size_t)rowA * TT;
    const int* m2 = m1 + 8 * (size_t)TT;
    const int* fl = g_mflag + (b * 16 + blockIdx.x) * 16;

    float o[8][4];
    #pragma unroll
    for (int i = 0; i < 8; i++)
        #pragma unroll
        for (int r = 0; r < 4; r++) o[i][r] = 0.f;
    float mA = -1e30f, mB = -1e30f, lA = 0.f, lB = 0.f;

    uint32_t qbase = smb + F_QHI
        + (wid * 16 + (lane & 7) + ((lane >> 3) & 1) * 8) * 144
        + ((lane >> 4) & 1) * 16;

    for (int jt = 0; jt < TT / KVR; jt++) {
        if (jt + 1 < TT / KVR) {
            LOAD_KV((jt + 1) * KVR, (jt + 1) & 1);
            CP_WAIT1();
        } else {
            CP_WAIT0();
        }
        __syncthreads();

        uint32_t sK = smb + (jt & 1) * KVSTG;
        uint32_t sV = sK + KVT;          // Vhi; Vlo at +KVT more

        // ---- S = Q K^T  (2-term: Qhi·Khi + Qlo·Khi) ----
        float s[8][4];
        #pragma unroll
        for (int i = 0; i < 8; i++)
            #pragma unroll
            for (int r = 0; r < 4; r++) s[i][r] = 0.f;

        #pragma unroll
        for (int ksp = 0; ksp < 2; ksp++) {
            uint32_t ah0[4], ah1[4], al0[4], al1[4];
            uint32_t qa = qbase + ksp * 64;
            LDMX4(ah0, qa);
            LDMX4(ah1, qa + 32);
            LDMX4(al0, qa + QTB);
            LDMX4(al1, qa + QTB + 32);
            #pragma unroll
            for (int nf = 0; nf < 8; nf++) {
                uint32_t kb[4];
                uint32_t ka = sK + (nf * 8 + (lane & 7)) * 144
                            + ksp * 64 + (lane >> 3) * 16;
                LDMX4(kb, ka);
                MMA16816(s[nf], ah0, &kb[0]);
                MMA16816(s[nf], al0, &kb[0]);
                MMA16816(s[nf], ah1, &kb[2]);
                MMA16816(s[nf], al1, &kb[2]);
            }
        }

        // ---- scale + mask (block-flag fast path) ----
        if (fl[jt >> 1]) {
            #pragma unroll
            for (int nf = 0; nf < 8; nf++) {
                s[nf][0] *= 0.125f; s[nf][1] *= 0.125f;
                s[nf][2] *= 0.125f; s[nf][3] *= 0.125f;
            }
        } else {
            int j0 = jt * KVR;
            #pragma unroll
            for (int nf = 0; nf < 8; nf++) {
                int jc = j0 + nf * 8 + 2 * (lane & 3);
                int2 ma = *(const int2*)(m1 + jc);
                int2 mb = *(const int2*)(m2 + jc);
                s[nf][0] = (ma.x == 0) ? -1e30f : s[nf][0] * 0.125f;
                s[nf][1] = (ma.y == 0) ? -1e30f : s[nf][1] * 0.125f;
                s[nf][2] = (mb.x == 0) ? -1e30f : s[nf][2] * 0.125f;
                s[nf][3] = (mb.y == 0) ? -1e30f : s[nf][3] * 0.125f;
            }
        }

        // ---- online softmax ----
        float tmA = -1e30f, tmB = -1e30f;
        #pragma unroll
        for (int nf = 0; nf < 8; nf++) {
            tmA = fmaxf(tmA, fmaxf(s[nf][0], s[nf][1]));
            tmB = fmaxf(tmB, fmaxf(s[nf][2], s[nf][3]));
        }
        #pragma unroll
        for (int off = 1; off <= 2; off <<= 1) {
            tmA = fmaxf(tmA, __shfl_xor_sync(0xffffffffu, tmA, off));
            tmB = fmaxf(tmB, __shfl_xor_sync(0xffffffffu, tmB, off));
        }
        float mnA = fmaxf(mA, tmA), mnB = fmaxf(mB, tmB);
        float aA = __expf(mA - mnA), aB = __expf(mB - mnB);
        mA = mnA; mB = mnB;

        float tsA = 0.f, tsB = 0.f;
        #pragma unroll
        for (int nf = 0; nf < 8; nf++) {
            s[nf][0] = __expf(s[nf][0] - mA);
            s[nf][1] = __expf(s[nf][1] - mA);
            s[nf][2] = __expf(s[nf][2] - mB);
            s[nf][3] = __expf(s[nf][3] - mB);
            tsA += s[nf][0] + s[nf][1];
            tsB += s[nf][2] + s[nf][3];
        }
        #pragma unroll
        for (int off = 1; off <= 2; off <<= 1) {
            tsA += __shfl_xor_sync(0xffffffffu, tsA, off);
            tsB += __shfl_xor_sync(0xffffffffu, tsB, off);
        }
        lA = lA * aA + tsA;
        lB = lB * aB + tsB;
        #pragma unroll
        for (int nf = 0; nf < 8; nf++) {
            o[nf][0] *= aA; o[nf][1] *= aA;
            o[nf][2] *= aB; o[nf][3] *= aB;
        }

        // ---- O += P V  (3-term: Phi·Vhi + Phi·Vlo + Plo·Vhi) ----
        #pragma unroll
        for (int ksp = 0; ksp < 2; ksp++) {
            uint32_t pah0[4], pal0[4], pah1[4], pal1[4];
            cvt2h(s[4*ksp+0][0], s[4*ksp+0][1], pah0[0], pal0[0]);
            cvt2h(s[4*ksp+0][2], s[4*ksp+0][3], pah0[1], pal0[1]);
            cvt2h(s[4*ksp+1][0], s[4*ksp+1][1], pah0[2], pal0[2]);
            cvt2h(s[4*ksp+1][2], s[4*ksp+1][3], pah0[3], pal0[3]);
            cvt2h(s[4*ksp+2][0], s[4*ksp+2][1], pah1[0], pal1[0]);
            cvt2h(s[4*ksp+2][2], s[4*ksp+2][3], pah1[1], pal1[1]);
            cvt2h(s[4*ksp+3][0], s[4*ksp+3][1], pah1[2], pal1[2]);
            cvt2h(s[4*ksp+3][2], s[4*ksp+3][3], pah1[3], pal1[3]);
            #pragma unroll
            for (int nf = 0; nf < 8; nf++) {
                uint32_t vh[4], vl[4];
                uint32_t va = sV + (ksp * 32 + lane) * 144 + nf * 16;
                LDMX4T(vh, va);
                LDMX4T(vl, va + KVT);
                MMA16816(o[nf], pah0, &vh[0]);
                MMA16816(o[nf], pah0, &vl[0]);
                MMA16816(o[nf], pal0, &vh[0]);
                MMA16816(o[nf], pah1, &vh[2]);
                MMA16816(o[nf], pah1, &vl[2]);
                MMA16816(o[nf], pal1, &vh[2]);
            }
        }
        __syncthreads();
    }

    // ---- epilogue: normalize, split to fp16 hi/lo in activation slice 0 ----
    float invA = 1.0f / lA, invB = 1.0f / lB;
    size_t base = ((size_t)b * TT + rowA) * D_MODEL + h * HD + 2 * (lane & 3);
    #pragma unroll
    for (int nf = 0; nf < 8; nf++) {
        uint32_t hi, lo;
        cvt2h(o[nf][0] * invA, o[nf][1] * invA, hi, lo);
        *(uint32_t*)(g_ahi + base + nf * 8) = hi;
        *(uint32_t*)(g_alo + base + nf * 8) = lo;
        cvt2h(o[nf][2] * invB, o[nf][3] * invB, hi, lo);
        *(uint32_t*)(g_ahi + base + 8 * D_MODEL + nf * 8) = hi;
        *(uint32_t*)(g_alo + base + 8 * D_MODEL + nf * 8) = lo;
    }
#undef LOAD_KV
}

// ---------------------------------------------------------------------------
extern "C" void kernel_launch(void* const* d_in, const int* in_sizes, int n_in,
                              void* d_out, int out_size)
{
    const float* query = (const float*)d_in[0];
    const float* key   = (const float*)d_in[1];
    const float* value = (const float*)d_in[2];
    const int*   mask  = (const int*)d_in[3];
    const float* wq = (const float*)d_in[4];
    const float* bq = (const float*)d_in[5];
    const float* wk = (const float*)d_in[6];
    const float* bk = (const float*)d_in[7];
    const float* wv = (const float*)d_in[8];
    const float* bv = (const float*)d_in[9];
    const float* wo = (const float*)d_in[10];
    const float* bo = (const float*)d_in[11];
    float* out = (float*)d_out;

    cudaFuncSetAttribute(tc_gemm_qk,
                         cudaFuncAttributeMaxDynamicSharedMemorySize, GEMM3_SMEM);
    cudaFuncSetAttribute(tc_gemm_v,
                         cudaFuncAttributeMaxDynamicSharedMemorySize, GEMM4_SMEM);
    cudaFuncSetAttribute(tc_gemm_o,
                         cudaFuncAttributeMaxDynamicSharedMemorySize, GEMM4_SMEM);
    cudaFuncSetAttribute(flash_attn,
                         cudaFuncAttributeMaxDynamicSharedMemorySize, FLASH_SMEM);

    prep_all<<<PREP_TOTAL, 256>>>(query, key, value, wq, wk, wv, wo, mask);

    tc_gemm_qk<<<dim3(8, 32, 2), 256, GEMM3_SMEM>>>(bq, bk);
    tc_gemm_v<<<dim3(8, 32), 256, GEMM4_SMEM>>>(bv);

    flash_attn<<<dim3(TT / 128, BB * NH), 256, FLASH_SMEM>>>(mask);

    tc_gemm_o<<<dim3(8, 32), 256, GEMM4_SMEM>>>(bo, out);
}

// round 17
// speedup vs baseline: 2.1700x; 1.1937x over previous
#include <cuda_runtime.h>
#include <cuda_fp16.h>
#include <cstdint>

#define D_MODEL 1024
#define NH 16
#define HD 64
#define BB 2
#define TT 2048
#define MTOT (BB*TT)   // 4096

// fp16 hi/lo split scratch: activations 3 slices (q,k,v; att reuses slice 0)
__device__ __half g_ahi[3*MTOT*D_MODEL];
__device__ __half g_alo[3*MTOT*D_MODEL];
// weight hi: 4 slices (wq, wk, wv, wo). No lo slices needed (all GEMMs 2-term).
__device__ __half g_whi[4*D_MODEL*D_MODEL];

// Q/K/V in (b,h,t,d) layout, fp16. Q hi+lo (QK^T 2-term on Q),
// K hi-only, V hi-only (PV 2-term on P).
__device__ __half g_Qhi[BB*NH*TT*HD];
__device__ __half g_Qlo[BB*NH*TT*HD];
__device__ __half g_Khi[BB*NH*TT*HD];
__device__ __half g_Vhi[BB*NH*TT*HD];

// mask block flags: [b][qt][kt] over 128x128 blocks, 1 = fully unmasked
__device__ int g_mflag[BB*16*16];

// ===========================================================================
// helpers
// ===========================================================================
__device__ __forceinline__ uint32_t smem_u32(const void* p) {
    uint32_t a;
    asm("{ .reg .u64 t; cvta.to.shared.u64 t, %1; cvt.u32.u64 %0, t; }"
        : "=r"(a) : "l"(p));
    return a;
}

__device__ __forceinline__ void cvt_split_h(float4 v, uint2& hi, uint2& lo) {
    __half2 h01 = __floats2half2_rn(v.x, v.y);
    __half2 h23 = __floats2half2_rn(v.z, v.w);
    float r0 = v.x - __low2float(h01);
    float r1 = v.y - __high2float(h01);
    float r2 = v.z - __low2float(h23);
    float r3 = v.w - __high2float(h23);
    __half2 l01 = __floats2half2_rn(r0, r1);
    __half2 l23 = __floats2half2_rn(r2, r3);
    hi.x = *(uint32_t*)&h01; hi.y = *(uint32_t*)&h23;
    lo.x = *(uint32_t*)&l01; lo.y = *(uint32_t*)&l23;
}

__device__ __forceinline__ void cvt2h(float a, float b, uint32_t& hi, uint32_t& lo) {
    __half2 h = __floats2half2_rn(a, b);
    float ra = a - __low2float(h);
    float rb = b - __high2float(h);
    __half2 l = __floats2half2_rn(ra, rb);
    hi = *(uint32_t*)&h; lo = *(uint32_t*)&l;
}

__device__ __forceinline__ uint32_t cvt1h(float a, float b) {
    __half2 h = __floats2half2_rn(a, b);
    return *(uint32_t*)&h;
}

#define LDMX4(r, addr) \
    asm volatile("ldmatrix.sync.aligned.m8n8.x4.shared.b16 {%0,%1,%2,%3}, [%4];" \
        : "=r"((r)[0]), "=r"((r)[1]), "=r"((r)[2]), "=r"((r)[3]) : "r"(addr))

#define LDMX4T(r, addr) \
    asm volatile("ldmatrix.sync.aligned.m8n8.x4.trans.shared.b16 {%0,%1,%2,%3}, [%4];" \
        : "=r"((r)[0]), "=r"((r)[1]), "=r"((r)[2]), "=r"((r)[3]) : "r"(addr))

#define MMA16816(c, a, b) \
    asm volatile("mma.sync.aligned.m16n8k16.row.col.f32.f16.f16.f32 " \
        "{%0,%1,%2,%3}, {%4,%5,%6,%7}, {%8,%9}, {%0,%1,%2,%3};" \
        : "+f"((c)[0]), "+f"((c)[1]), "+f"((c)[2]), "+f"((c)[3]) \
        : "r"((a)[0]), "r"((a)[1]), "r"((a)[2]), "r"((a)[3]), \
          "r"((b)[0]), "r"((b)[1]))

#define CP_ASYNC16(dst, src) \
    asm volatile("cp.async.cg.shared.global [%0], [%1], 16;" \
        :: "r"(dst), "l"(src))
#define CP_COMMIT() asm volatile("cp.async.commit_group;" ::: "memory")
#define CP_WAIT1()  asm volatile("cp.async.wait_group 1;" ::: "memory")
#define CP_WAIT0()  asm volatile("cp.async.wait_group 0;" ::: "memory")

// ===========================================================================
// Fused prep: weight hi splits + activation splits + mask block flags.
// ===========================================================================
#define PREP_ACT_BLKS (3*4096)
#define PREP_W_BLKS   (4*1024)
#define PREP_TOTAL (PREP_ACT_BLKS + PREP_W_BLKS + 512)

__global__ void __launch_bounds__(256) prep_all(
    const float* __restrict__ q, const float* __restrict__ k,
    const float* __restrict__ v,
    const float* __restrict__ wq, const float* __restrict__ wk,
    const float* __restrict__ wv, const float* __restrict__ wo,
    const int* __restrict__ mask)
{
    int bid = blockIdx.x;
    int tid = threadIdx.x;

    if (bid < PREP_ACT_BLKS) {
        int z = bid >> 12;
        int i = (bid & 4095) * 256 + tid;
        const float* src = (z == 0) ? q : (z == 1) ? k : v;
        float4 val = ((const float4*)src)[i];
        uint2 hi, lo;
        cvt_split_h(val, hi, lo);
        size_t off = (size_t)z * (MTOT * D_MODEL / 4) + i;
        ((uint2*)g_ahi)[off] = hi;
        ((uint2*)g_alo)[off] = lo;
    } else if (bid < PREP_ACT_BLKS + PREP_W_BLKS) {
        int r = bid - PREP_ACT_BLKS;
        int z = r >> 10;
        int i = (r & 1023) * 256 + tid;
        const float* src = (z == 0) ? wq : (z == 1) ? wk : (z == 2) ? wv : wo;
        float4 val = ((const float4*)src)[i];
        __half2 h01 = __floats2half2_rn(val.x, val.y);
        __half2 h23 = __floats2half2_rn(val.z, val.w);
        uint2 hi;
        hi.x = *(uint32_t*)&h01; hi.y = *(uint32_t*)&h23;
        ((uint2*)g_whi)[(size_t)z * (D_MODEL * D_MODEL / 4) + i] = hi;
    } else {
        int r = bid - PREP_ACT_BLKS - PREP_W_BLKS;   // 0..511
        int qt = r & 15, kt = (r >> 4) & 15, b = r >> 8;
        const int* mp = mask + ((size_t)b * TT + qt * 128) * TT + kt * 128;
        int row = tid >> 1, ch = (tid & 1) * 64;
        bool ok = true;
        #pragma unroll
        for (int i = 0; i < 16; i++) {
            int4 vv = *(const int4*)(mp + (size_t)row * TT + ch + i * 4);
            ok = ok && vv.x && vv.y && vv.z && vv.w;
        }
        int all = __syncthreads_and((int)ok);
        if (tid == 0) g_mflag[(b * 16 + qt) * 16 + kt] = all;
    }
}

// ===========================================================================
// HMMA GEMM, 3-tile 2-term (Ahi+Alo vs Whi) — R15-proven.
// ===========================================================================
#define LDSB 80
#define TILE_B (128*LDSB)
#define STAGE3_B (3*TILE_B)
#define GEMM3_SMEM (2*STAGE3_B)   // 61440

#define GEMM_LOAD3(kc, stg) do {                                              \
    uint32_t sb0 = smb + (stg) * STAGE3_B;                                    \
    if (tid < 128) {                                                          \
        int tl = tid >> 6, lt = tid & 63;                                     \
        const __half* sp = tl ? lsAlo : lsAhi;                                \
        _Pragma("unroll")                                                     \
        for (int j = 0; j < 8; j++) {                                         \
            int rem = lt + j * 64;                                            \
            int row = rem >> 2, cc = rem & 3;                                 \
            CP_ASYNC16(sb0 + tl * TILE_B + row * LDSB + cc * 16,              \
                       sp + (size_t)(m0 + row) * D_MODEL + (kc) * 32 + cc * 8); \
        }                                                                     \
    } else {                                                                  \
        int lt = tid - 128;                                                   \
        _Pragma("unroll")                                                     \
        for (int j = 0; j < 4; j++) {                                         \
            int rem = lt + j * 128;                                           \
            int row = rem >> 2, cc = rem & 3;                                 \
            CP_ASYNC16(sb0 + 2 * TILE_B + row * LDSB + cc * 16,               \
                       lsW + (size_t)(n0 + row) * D_MODEL + (kc) * 32 + cc * 8); \
        }                                                                     \
    }                                                                         \
    CP_COMMIT();                                                              \
} while (0)

#define GEMM_MAIN3()                                                          \
    uint32_t arow = warp_m * 64 + (lane & 7) + ((lane >> 3) & 1) * 8;         \
    uint32_t acol = ((lane >> 4) & 1) * 16;                                   \
    uint32_t brow2 = warp_n * 32 + ((lane >> 4) & 1) * 8 + (lane & 7);        \
    uint32_t bcol2 = ((lane >> 3) & 1) * 16;                                  \
    GEMM_LOAD3(0, 0);                                                         \
    for (int kc = 0; kc < D_MODEL / 32; kc++) {                               \
        if (kc + 1 < D_MODEL / 32) { GEMM_LOAD3(kc + 1, (kc + 1) & 1); CP_WAIT1(); } \
        else { CP_WAIT0(); }                                                  \
        __syncthreads();                                                      \
        uint32_t sb = smb + (kc & 1) * STAGE3_B;                              \
        uint32_t abase = sb + arow * LDSB + acol;                             \
        uint32_t bbase = sb + 2 * TILE_B + brow2 * LDSB + bcol2;              \
        _Pragma("unroll")                                                     \
        for (int s = 0; s < 2; s++) {                                         \
            uint32_t bh4[2][4];                                               \
            _Pragma("unroll")                                                 \
            for (int jp = 0; jp < 2; jp++)                                    \
                LDMX4(bh4[jp], bbase + jp * 16 * LDSB + s * 32);              \
            _Pragma("unroll")                                                 \
            for (int im = 0; im < 4; im++) {                                  \
                uint32_t ah[4], al[4];                                        \
                uint32_t ad = abase + im * 16 * LDSB + s * 32;                \
                LDMX4(ah, ad);                                                \
                LDMX4(al, ad + TILE_B);                                       \
                _Pragma("unroll")                                             \
                for (int jp = 0; jp < 2; jp++) {                              \
                    MMA16816(acc[im][2*jp],   ah, &bh4[jp][0]);               \
                    MMA16816(acc[im][2*jp],   al, &bh4[jp][0]);               \
                    MMA16816(acc[im][2*jp+1], ah, &bh4[jp][2]);               \
                    MMA16816(acc[im][2*jp+1], al, &bh4[jp][2]);               \
                }                                                             \
            }                                                                 \
        }                                                                     \
        __syncthreads();                                                      \
    }

// Q/K/V projections, 2-term: grid (8, 32, 3)
__global__ void __launch_bounds__(256, 2) tc_gemm_qkv(
    const float* __restrict__ bq, const float* __restrict__ bk,
    const float* __restrict__ bv)
{
    extern __shared__ char smc[];
    uint32_t smb = smem_u32(smc);
    int tid = threadIdx.x;
    int lane = tid & 31;
    int wid = tid >> 5;
    int warp_m = wid & 1;
    int warp_n = wid >> 1;
    int m0 = blockIdx.y * 128;
    int n0 = blockIdx.x * 128;
    int z = blockIdx.z;
    const float* bias = (z == 0) ? bq : (z == 1) ? bk : bv;

    const __half* lsAhi = g_ahi + (size_t)z * MTOT * D_MODEL;
    const __half* lsAlo = g_alo + (size_t)z * MTOT * D_MODEL;
    const __half* lsW   = g_whi + (size_t)z * D_MODEL * D_MODEL;

    float acc[4][4][4];
    #pragma unroll
    for (int i = 0; i < 4; i++)
        #pragma unroll
        for (int j = 0; j < 4; j++)
            #pragma unroll
            for (int r = 0; r < 4; r++) acc[i][j][r] = 0.f;

    GEMM_MAIN3();

    __half* dhi = (z == 0) ? g_Qhi : (z == 1) ? g_Khi : g_Vhi;
    #pragma unroll
    for (int im = 0; im < 4; im++) {
        #pragma unroll
        for (int jn = 0; jn < 4; jn++) {
            int m = m0 + warp_m * 64 + im * 16 + (lane >> 2);
            int n = n0 + warp_n * 32 + jn * 8 + (lane & 3) * 2;
            float2 bv2 = *(const float2*)&bias[n];
            float2 v01 = make_float2(acc[im][jn][0] + bv2.x, acc[im][jn][1] + bv2.y);
            float2 v23 = make_float2(acc[im][jn][2] + bv2.x, acc[im][jn][3] + bv2.y);
            int h = n >> 6, d = n & 63;
            int b = m >> 11, t = m & 2047;
            size_t off = (((size_t)b * NH + h) * TT + t) * HD + d;
            if (z == 0) {
                uint32_t hi0, lo0, hi1, lo1;
                cvt2h(v01.x, v01.y, hi0, lo0);
                cvt2h(v23.x, v23.y, hi1, lo1);
                *(uint32_t*)(dhi + off) = hi0;
                *(uint32_t*)(dhi + off + 8 * HD) = hi1;
                *(uint32_t*)(g_Qlo + off) = lo0;
                *(uint32_t*)(g_Qlo + off + 8 * HD) = lo1;
            } else {
                *(uint32_t*)(dhi + off) = cvt1h(v01.x, v01.y);
                *(uint32_t*)(dhi + off + 8 * HD) = cvt1h(v23.x, v23.y);
            }
        }
    }
}

// Output projection, 2-term: grid (8, 32), fp32 flat out
__global__ void __launch_bounds__(256, 2) tc_gemm_o(
    const float* __restrict__ bias, float* __restrict__ Cflat)
{
    extern __shared__ char smc[];
    uint32_t smb = smem_u32(smc);
    int tid = threadIdx.x;
    int lane = tid & 31;
    int wid = tid >> 5;
    int warp_m = wid & 1;
    int warp_n = wid >> 1;
    int m0 = blockIdx.y * 128;
    int n0 = blockIdx.x * 128;

    const __half* lsAhi = g_ahi;
    const __half* lsAlo = g_alo;
    const __half* lsW   = g_whi + (size_t)3 * D_MODEL * D_MODEL;

    float acc[4][4][4];
    #pragma unroll
    for (int i = 0; i < 4; i++)
        #pragma unroll
        for (int j = 0; j < 4; j++)
            #pragma unroll
            for (int r = 0; r < 4; r++) acc[i][j][r] = 0.f;

    GEMM_MAIN3();

    #pragma unroll
    for (int im = 0; im < 4; im++) {
        #pragma unroll
        for (int jn = 0; jn < 4; jn++) {
            int m = m0 + warp_m * 64 + im * 16 + (lane >> 2);
            int n = n0 + warp_n * 32 + jn * 8 + (lane & 3) * 2;
            float2 bv2 = *(const float2*)&bias[n];
            *(float2*)(Cflat + (size_t)m * D_MODEL + n) =
                make_float2(acc[im][jn][0] + bv2.x, acc[im][jn][1] + bv2.y);
            *(float2*)(Cflat + (size_t)(m + 8) * D_MODEL + n) =
                make_float2(acc[im][jn][2] + bv2.x, acc[im][jn][3] + bv2.y);
        }
    }
}

// ===========================================================================
// HMMA flash attention, fp16. QK^T 2-term (Qhi,Qlo x Khi), PV 2-term
// (Phi,Plo x Vhi). KV stage = Khi, Vhi (2 tiles). 64-key tiles, 2 CTAs/SM.
// ===========================================================================
#define KVR 64
#define KVT (KVR*144)              // 9216
#define KVSTG (2*KVT)              // 18432
#define QTB 18432                  // 128 x 144
#define F_QHI (2*KVSTG)            // 36864
#define F_QLO (F_QHI + QTB)
#define FLASH_SMEM (F_QLO + QTB)   // 73728

__global__ void __launch_bounds__(256, 2) flash_attn(const int* __restrict__ mask)
{
    extern __shared__ char smc[];
    uint32_t smb = smem_u32(smc);
    int tid = threadIdx.x;
    int lane = tid & 31;
    int wid = tid >> 5;

    int bh = blockIdx.y;
    int b = bh >> 4;
    int h = bh & 15;
    int q0 = blockIdx.x * 128;

    // stage Q (hi+lo) once
    #pragma unroll
    for (int i = 0; i < 8; i++) {
        int c = tid + i * 256;
        int tens = c >> 10, c2 = c & 1023;
        int row = c2 >> 3, ch = c2 & 7;
        const __half* src = (tens ? g_Qlo : g_Qhi)
            + ((size_t)bh * TT + q0 + row) * HD + ch * 8;
        CP_ASYNC16(smb + F_QHI + tens * QTB + row * 144 + ch * 16, src);
    }
    CP_COMMIT();

    const __half* kKhi = g_Khi + (size_t)bh * TT * HD;
    const __half* kVhi = g_Vhi + (size_t)bh * TT * HD;

#define LOAD_KV(j0, stg) do {                                                 \
    uint32_t dstb = smb + (stg) * KVSTG;                                      \
    _Pragma("unroll")                                                         \
    for (int i = 0; i < 4; i++) {                                             \
        const __half* sp = (i < 2) ? kKhi : kVhi;                             \
        int rem = tid + (i & 1) * 256;                                        \
        int row = rem >> 3, ch = rem & 7;                                     \
        CP_ASYNC16(dstb + (i >> 1) * KVT + row * 144 + ch * 16,               \
                   sp + (size_t)((j0) + row) * HD + ch * 8);                  \
    }                                                                         \
    CP_COMMIT();                                                              \
} while (0)

    LOAD_KV(0, 0);

    int rowA = q0 + wid * 16 + (lane >> 2);
    const int* m1 = mask + (size_t)b * TT * TT + (size_t)rowA * TT;
    const int* m2 = m1 + 8 * (size_t)TT;
    const int* fl = g_mflag + (b * 16 + blockIdx.x) * 16;

    float o[8][4];
    #pragma unroll
    for (int i = 0; i < 8; i++)
        #pragma unroll
        for (int r = 0; r < 4; r++) o[i][r] = 0.f;
    float mA = -1e30f, mB = -1e30f, lA = 0.f, lB = 0.f;

    uint32_t qbase = smb + F_QHI
        + (wid * 16 + (lane & 7) + ((lane >> 3) & 1) * 8) * 144
        + ((lane >> 4) & 1) * 16;

    for (int jt = 0; jt < TT / KVR; jt++) {
        if (jt + 1 < TT / KVR) {
            LOAD_KV((jt + 1) * KVR, (jt + 1) & 1);
            CP_WAIT1();
        } else {
            CP_WAIT0();
        }
        __syncthreads();

        uint32_t sK = smb + (jt & 1) * KVSTG;
        uint32_t sV = sK + KVT;

        // ---- S = Q K^T  (2-term: Qhi·Khi + Qlo·Khi) ----
        float s[8][4];
        #pragma unroll
        for (int i = 0; i < 8; i++)
            #pragma unroll
            for (int r = 0; r < 4; r++) s[i][r] = 0.f;

        #pragma unroll
        for (int ksp = 0; ksp < 2; ksp++) {
            uint32_t ah0[4], ah1[4], al0[4], al1[4];
            uint32_t qa = qbase + ksp * 64;
            LDMX4(ah0, qa);
            LDMX4(ah1, qa + 32);
            LDMX4(al0, qa + QTB);
            LDMX4(al1, qa + QTB + 32);
            #pragma unroll
            for (int nf = 0; nf < 8; nf++) {
                uint32_t kb[4];
                uint32_t ka = sK + (nf * 8 + (lane & 7)) * 144
                            + ksp * 64 + (lane >> 3) * 16;
                LDMX4(kb, ka);
                MMA16816(s[nf], ah0, &kb[0]);
                MMA16816(s[nf], al0, &kb[0]);
                MMA16816(s[nf], ah1, &kb[2]);
                MMA16816(s[nf], al1, &kb[2]);
            }
        }

        // ---- scale + mask (block-flag fast path) ----
        if (fl[jt >> 1]) {
            #pragma unroll
            for (int nf = 0; nf < 8; nf++) {
                s[nf][0] *= 0.125f; s[nf][1] *= 0.125f;
                s[nf][2] *= 0.125f; s[nf][3] *= 0.125f;
            }
        } else {
            int j0 = jt * KVR;
            #pragma unroll
            for (int nf = 0; nf < 8; nf++) {
                int jc = j0 + nf * 8 + 2 * (lane & 3);
                int2 ma = *(const int2*)(m1 + jc);
                int2 mb = *(const int2*)(m2 + jc);
                s[nf][0] = (ma.x == 0) ? -1e30f : s[nf][0] * 0.125f;
                s[nf][1] = (ma.y == 0) ? -1e30f : s[nf][1] * 0.125f;
                s[nf][2] = (mb.x == 0) ? -1e30f : s[nf][2] * 0.125f;
                s[nf][3] = (mb.y == 0) ? -1e30f : s[nf][3] * 0.125f;
            }
        }

        // ---- online softmax ----
        float tmA = -1e30f, tmB = -1e30f;
        #pragma unroll
        for (int nf = 0; nf < 8; nf++) {
            tmA = fmaxf(tmA, fmaxf(s[nf][0], s[nf][1]));
            tmB = fmaxf(tmB, fmaxf(s[nf][2], s[nf][3]));
        }
        #pragma unroll
        for (int off = 1; off <= 2; off <<= 1) {
            tmA = fmaxf(tmA, __shfl_xor_sync(0xffffffffu, tmA, off));
            tmB = fmaxf(tmB, __shfl_xor_sync(0xffffffffu, tmB, off));
        }
        float mnA = fmaxf(mA, tmA), mnB = fmaxf(mB, tmB);
        float aA = __expf(mA - mnA), aB = __expf(mB - mnB);
        mA = mnA; mB = mnB;

        float tsA = 0.f, tsB = 0.f;
        #pragma unroll
        for (int nf = 0; nf < 8; nf++) {
            s[nf][0] = __expf(s[nf][0] - mA);
            s[nf][1] = __expf(s[nf][1] - mA);
            s[nf][2] = __expf(s[nf][2] - mB);
            s[nf][3] = __expf(s[nf][3] - mB);
            tsA += s[nf][0] + s[nf][1];
            tsB += s[nf][2] + s[nf][3];
        }
        #pragma unroll
        for (int off = 1; off <= 2; off <<= 1) {
            tsA += __shfl_xor_sync(0xffffffffu, tsA, off);
            tsB += __shfl_xor_sync(0xffffffffu, tsB, off);
        }
        lA = lA * aA + tsA;
        lB = lB * aB + tsB;
        #pragma unroll
        for (int nf = 0; nf < 8; nf++) {
            o[nf][0] *= aA; o[nf][1] *= aA;
            o[nf][2] *= aB; o[nf][3] *= aB;
        }

        // ---- O += P V  (2-term: Phi·Vhi + Plo·Vhi) ----
        #pragma unroll
        for (int ksp = 0; ksp < 2; ksp++) {
            uint32_t pah0[4], pal0[4], pah1[4], pal1[4];
            cvt2h(s[4*ksp+0][0], s[4*ksp+0][1], pah0[0], pal0[0]);
            cvt2h(s[4*ksp+0][2], s[4*ksp+0][3], pah0[1], pal0[1]);
            cvt2h(s[4*ksp+1][0], s[4*ksp+1][1], pah0[2], pal0[2]);
            cvt2h(s[4*ksp+1][2], s[4*ksp+1][3], pah0[3], pal0[3]);
            cvt2h(s[4*ksp+2][0], s[4*ksp+2][1], pah1[0], pal1[0]);
            cvt2h(s[4*ksp+2][2], s[4*ksp+2][3], pah1[1], pal1[1]);
            cvt2h(s[4*ksp+3][0], s[4*ksp+3][1], pah1[2], pal1[2]);
            cvt2h(s[4*ksp+3][2], s[4*ksp+3][3], pah1[3], pal1[3]);
            #pragma unroll
            for (int nf = 0; nf < 8; nf++) {
                uint32_t vh[4];
                uint32_t va = sV + (ksp * 32 + lane) * 144 + nf * 16;
                LDMX4T(vh, va);
                MMA16816(o[nf], pah0, &vh[0]);
                MMA16816(o[nf], pal0, &vh[0]);
                MMA16816(o[nf], pah1, &vh[2]);
                MMA16816(o[nf], pal1, &vh[2]);
            }
        }
        __syncthreads();
    }

    // ---- epilogue: normalize, split to fp16 hi/lo in activation slice 0 ----
    float invA = 1.0f / lA, invB = 1.0f / lB;
    size_t base = ((size_t)b * TT + rowA) * D_MODEL + h * HD + 2 * (lane & 3);
    #pragma unroll
    for (int nf = 0; nf < 8; nf++) {
        uint32_t hi, lo;
        cvt2h(o[nf][0] * invA, o[nf][1] * invA, hi, lo);
        *(uint32_t*)(g_ahi + base + nf * 8) = hi;
        *(uint32_t*)(g_alo + base + nf * 8) = lo;
        cvt2h(o[nf][2] * invB, o[nf][3] * invB, hi, lo);
        *(uint32_t*)(g_ahi + base + 8 * D_MODEL + nf * 8) = hi;
        *(uint32_t*)(g_alo + base + 8 * D_MODEL + nf * 8) = lo;
    }
#undef LOAD_KV
}

// ---------------------------------------------------------------------------
extern "C" void kernel_launch(void* const* d_in, const int* in_sizes, int n_in,
                              void* d_out, int out_size)
{
    const float* query = (const float*)d_in[0];
    const float* key   = (const float*)d_in[1];
    const float* value = (const float*)d_in[2];
    const int*   mask  = (const int*)d_in[3];
    const float* wq = (const float*)d_in[4];
    const float* bq = (const float*)d_in[5];
    const float* wk = (const float*)d_in[6];
    const float* bk = (const float*)d_in[7];
    const float* wv = (const float*)d_in[8];
    const float* bv = (const float*)d_in[9];
    const float* wo = (const float*)d_in[10];
    const float* bo = (const float*)d_in[11];
    float* out = (float*)d_out;

    cudaFuncSetAttribute(tc_gemm_qkv,
                         cudaFuncAttributeMaxDynamicSharedMemorySize, GEMM3_SMEM);
    cudaFuncSetAttribute(tc_gemm_o,
                         cudaFuncAttributeMaxDynamicSharedMemorySize, GEMM3_SMEM);
    cudaFuncSetAttribute(flash_attn,
                         cudaFuncAttributeMaxDynamicSharedMemorySize, FLASH_SMEM);

    prep_all<<<PREP_TOTAL, 256>>>(query, key, value, wq, wk, wv, wo, mask);

    tc_gemm_qkv<<<dim3(8, 32, 3), 256, GEMM3_SMEM>>>(bq, bk, bv);

    flash_attn<<<dim3(TT / 128, BB * NH), 256, FLASH_SMEM>>>(mask);

    tc_gemm_o<<<dim3(8, 32), 256, GEMM3_SMEM>>>(bo, out);
}